// round 11
// baseline (speedup 1.0000x reference)
#include <cuda_runtime.h>
#include <cuda_bf16.h>
#include <cuda_fp16.h>
#include <cstdint>

#define NTX_MAX 100000
#define NM_MAX  20000
#define E_MAX   500000

typedef __nv_bfloat16 bf16;

// ---------------- scratch ----------------
__device__ float  g_q_tx [(size_t)NTX_MAX * 64];
__device__ float  g_q_m  [(size_t)NM_MAX  * 64];
__device__ __half g_kv_tx[(size_t)NTX_MAX * 128];
__device__ __half g_kv_m [(size_t)NM_MAX  * 128];
__device__ float  g_h_tx [(size_t)NTX_MAX * 64];     // fp32 (skip input)
// pre-split bf16 activations
__device__ bf16 g_xh_tx[(size_t)NTX_MAX * 128]; __device__ bf16 g_xl_tx[(size_t)NTX_MAX * 128];
__device__ bf16 g_xh_m [(size_t)NM_MAX  * 128]; __device__ bf16 g_xl_m [(size_t)NM_MAX  * 128];
__device__ bf16 g_aggh_tx[(size_t)NTX_MAX * 64]; __device__ bf16 g_aggl_tx[(size_t)NTX_MAX * 64];
__device__ bf16 g_aggh_m [(size_t)NM_MAX  * 64]; __device__ bf16 g_aggl_m [(size_t)NM_MAX  * 64];
__device__ bf16 g_hh_tx[(size_t)NTX_MAX * 64]; __device__ bf16 g_hl_tx[(size_t)NTX_MAX * 64];
__device__ bf16 g_hh_m [(size_t)NM_MAX  * 64]; __device__ bf16 g_hl_m [(size_t)NM_MAX  * 64];
// pre-split weights
__device__ bf16 g_Wh1A[128*192]; __device__ bf16 g_Wl1A[128*192];
__device__ bf16 g_Wh1B[128*192]; __device__ bf16 g_Wl1B[128*192];
__device__ bf16 g_Wh2A[128*192]; __device__ bf16 g_Wl2A[128*192];
__device__ bf16 g_Wh2B[128*192]; __device__ bf16 g_Wl2B[128*192];
__device__ bf16 g_WaH[3*4096];   __device__ bf16 g_WaL[3*4096];
__device__ float g_bA1[192]; __device__ float g_bB1[192];
__device__ float g_bA2[192]; __device__ float g_bB2[192];
// CSR
__device__ int g_rowptr0[NM_MAX + 1];
__device__ int g_rowptr1[NTX_MAX + 1];
__device__ int g_cursor0[NM_MAX];
__device__ int g_cursor1[NTX_MAX];
__device__ int g_srcs0[E_MAX];
__device__ int g_srcs1[E_MAX];

// ---------------- helpers ----------------
__device__ __forceinline__ void split2(float x, float y, uint32_t& hi, uint32_t& lo) {
    bf16 hx = __float2bfloat16_rn(x), hy = __float2bfloat16_rn(y);
    bf16 lx = __float2bfloat16_rn(x - __bfloat162float(hx));
    bf16 ly = __float2bfloat16_rn(y - __bfloat162float(hy));
    __nv_bfloat162 h2 = __halves2bfloat162(hx, hy);
    __nv_bfloat162 l2 = __halves2bfloat162(lx, ly);
    hi = *(uint32_t*)&h2;
    lo = *(uint32_t*)&l2;
}
__device__ __forceinline__ float gelu_exact(float v) {
    return 0.5f * v * (1.f + erff(v * 0.70710678118654752f));
}

// ---------------- CSR build ----------------
__global__ void hist_both_kernel(const int* __restrict__ d0, int E0, int* __restrict__ c0,
                                 const int* __restrict__ d1, int E1, int* __restrict__ c1) {
    int e = blockIdx.x * blockDim.x + threadIdx.x;
    if (e < E0) atomicAdd(&c0[d0[e]], 1);
    else if (e < E0 + E1) atomicAdd(&c1[d1[e - E0]], 1);
}

__global__ void scan_both_kernel(int* __restrict__ cnt0, int* __restrict__ rp0, int n0,
                                 int* __restrict__ cnt1, int* __restrict__ rp1, int n1) {
    __shared__ int ssum[1024];
    int* cnt = blockIdx.x ? cnt1 : cnt0;
    int* rowptr = blockIdx.x ? rp1 : rp0;
    int n = blockIdx.x ? n1 : n0;
    int tid = threadIdx.x;
    int chunk = (n + 1023) / 1024;
    int start = tid * chunk;
    int end = start + chunk; if (end > n) end = n; if (start > n) start = n;
    int s = 0;
    for (int i = start; i < end; i++) s += cnt[i];
    ssum[tid] = s;
    __syncthreads();
    for (int off = 1; off < 1024; off <<= 1) {
        int v = (tid >= off) ? ssum[tid - off] : 0;
        __syncthreads();
        ssum[tid] += v;
        __syncthreads();
    }
    int run = (tid == 0) ? 0 : ssum[tid - 1];
    for (int i = start; i < end; i++) {
        int c = cnt[i];
        rowptr[i] = run;
        cnt[i] = run;
        run += c;
    }
    if (tid == 1023) rowptr[n] = run;
}

// ---------------- prep: weights (bf16 split) + Wa split + zero + x split ----------------
struct PrepJob {
    const float *Wq1,*bq1,*Wk1,*bk1,*Wv1,*bv1,*a1,*m1;
    const float *Wq2,*bq2,*Wk2,*bk2,*Wv2,*bv2,*a2,*m2;
    const float *Wa1, *Wa2;
    const float *x_tx, *x_m;
    bf16 *Wh1A,*Wl1A,*Wh1B,*Wl1B,*Wh2A,*Wl2A,*Wh2B,*Wl2B;
    float *bA1,*bB1,*bA2,*bB2;
    bf16 *WaH,*WaL;
    bf16 *xh_tx,*xl_tx,*xh_m,*xl_m;
    int *cur0, *cur1;
    int nm, ntx;
    int c4, c5;  // zero end, wa end
};

__global__ void prep_kernel(PrepJob P) {
    int b = blockIdx.x, t = threadIdx.x;
    if (b < 292) {
        // effective fused QKV weights, split to bf16 hi/lo
        int layer, typ, base;
        if (b < 97)       { layer = 0; typ = 0; base = b; }
        else if (b < 194) { layer = 0; typ = 1; base = b - 97; }
        else if (b < 243) { layer = 1; typ = 0; base = b - 194; }
        else              { layer = 1; typ = 1; base = b - 243; }
        int din = layer ? 64 : 128;
        int idx = base * 256 + t;
        if (idx >= (din + 1) * 192) return;
        const float* Wq = layer ? P.Wq2 : P.Wq1;  const float* bq = layer ? P.bq2 : P.bq1;
        const float* Wk = layer ? P.Wk2 : P.Wk1;  const float* bk = layer ? P.bk2 : P.bk1;
        const float* Wv = layer ? P.Wv2 : P.Wv1;  const float* bv = layer ? P.bv2 : P.bv1;
        const float* ar = layer ? P.a2 : P.a1;    const float* mr = layer ? P.m2 : P.m1;
        Wq += (size_t)typ * din * 64; bq += typ * 64;
        Wk += (size_t)typ * din * 64; bk += typ * 64;
        Wv += (size_t)typ * din * 64; bv += typ * 64;
        ar += typ * 1024; mr += typ * 1024;
        bf16* Wh = layer ? (typ ? P.Wh2B : P.Wh2A) : (typ ? P.Wh1B : P.Wh1A);
        bf16* Wl = layer ? (typ ? P.Wl2B : P.Wl2A) : (typ ? P.Wl1B : P.Wl1A);
        float* bout = layer ? (typ ? P.bB2 : P.bA2) : (typ ? P.bB1 : P.bA1);
        int i = idx / 192, c = idx % 192;
        bool isBias = (i == din);
        float val;
        if (c < 64) {
            val = isBias ? bq[c] : Wq[i * 64 + c];
        } else {
            int cc = c - 64;
            bool isV = (cc >= 64);
            if (isV) cc -= 64;
            int h = cc >> 4, e = cc & 15;
            const float* rel  = isV ? mr : ar;
            const float* Wsrc = isV ? Wv : Wk;
            const float* bsrc = isV ? bv : bk;
            float s = 0.f;
            #pragma unroll
            for (int d = 0; d < 16; d++) {
                float w = isBias ? bsrc[h * 16 + d] : Wsrc[i * 64 + h * 16 + d];
                s += w * rel[h * 256 + d * 16 + e];
            }
            val = s;
        }
        if (isBias) bout[c] = val;
        else {
            bf16 hv = __float2bfloat16_rn(val);
            Wh[i * 192 + c] = hv;
            Wl[i * 192 + c] = __float2bfloat16_rn(val - __bfloat162float(hv));
        }
    } else if (b < P.c4) {
        int idx = (b - 292) * 256 + t;
        if (idx < P.nm) P.cur0[idx] = 0;
        else if (idx < P.nm + P.ntx) P.cur1[idx - P.nm] = 0;
    } else if (b < P.c5) {
        int idx = (b - P.c4) * 256 + t;
        if (idx >= 12288) return;
        int which = idx >> 12, e = idx & 4095;
        float val = (which == 2) ? P.Wa2[e] : P.Wa1[which * 4096 + e];
        bf16 hv = __float2bfloat16_rn(val);
        P.WaH[idx] = hv;
        P.WaL[idx] = __float2bfloat16_rn(val - __bfloat162float(hv));
    } else {
        // x split: float4 granules
        int idx4 = (b - P.c5) * 256 + t;
        int ntx4 = P.ntx * 32;
        const float* src; bf16 *dh, *dl; int j4;
        if (idx4 < ntx4) { src = P.x_tx; dh = P.xh_tx; dl = P.xl_tx; j4 = idx4; }
        else {
            j4 = idx4 - ntx4;
            if (j4 >= P.nm * 32) return;
            src = P.x_m; dh = P.xh_m; dl = P.xl_m;
        }
        float4 v = ((const float4*)src)[j4];
        uint32_t h0, l0, h1, l1;
        split2(v.x, v.y, h0, l0);
        split2(v.z, v.w, h1, l1);
        ((uint2*)dh)[j4] = make_uint2(h0, h1);
        ((uint2*)dl)[j4] = make_uint2(l0, l1);
    }
}

// ---------------- tensor-core GEMM: cp.async double-buffered, pre-split bf16 inputs ----------------
__device__ __forceinline__ void ldsm_x4(uint32_t* r, uint32_t addr) {
    asm volatile("ldmatrix.sync.aligned.m8n8.x4.shared.b16 {%0,%1,%2,%3}, [%4];"
        : "=r"(r[0]), "=r"(r[1]), "=r"(r[2]), "=r"(r[3]) : "r"(addr));
}
__device__ __forceinline__ void ldsm_x4_t(uint32_t* r, uint32_t addr) {
    asm volatile("ldmatrix.sync.aligned.m8n8.x4.trans.shared.b16 {%0,%1,%2,%3}, [%4];"
        : "=r"(r[0]), "=r"(r[1]), "=r"(r[2]), "=r"(r[3]) : "r"(addr));
}
__device__ __forceinline__ void mma_bf16(float* c, const uint32_t* a, uint32_t b0, uint32_t b1) {
    asm volatile("mma.sync.aligned.m16n8k16.row.col.f32.bf16.bf16.f32 "
        "{%0,%1,%2,%3}, {%4,%5,%6,%7}, {%8,%9}, {%0,%1,%2,%3};"
        : "+f"(c[0]), "+f"(c[1]), "+f"(c[2]), "+f"(c[3])
        : "r"(a[0]), "r"(a[1]), "r"(a[2]), "r"(a[3]), "r"(b0), "r"(b1));
}
__device__ __forceinline__ void cp16(uint32_t saddr, const void* gptr, int szr) {
    asm volatile("cp.async.cg.shared.global [%0], [%1], 16, %2;"
        :: "r"(saddr), "l"(gptr), "r"(szr) : "memory");
}
#define CP_COMMIT() asm volatile("cp.async.commit_group;" ::: "memory")
#define CP_WAIT(n)  asm volatile("cp.async.wait_group %0;" :: "n"(n) : "memory")

#define AS_STRIDE 40

struct GemmJob {
    const bf16 *Ah, *Al, *Bh, *Bl;
    const float* bias; const float* x_in;
    float* outF; __half* outH; bf16 *outBh, *outBl;
    int N, lda, ldb, col0, ldo, colBlocks;
};

struct ScatJob {
    const int* s0; const int* d0; int E0; int* cur0; int* out0;
    const int* s1; const int* d1; int E1; int* cur1; int* out1;
    int nblocks;
};

template <int POST, int NCOLS, int SCAT, int FINAL>
__global__ __launch_bounds__(256) void mma_gemm_kernel(
    GemmJob j0, GemmJob j1, int nb0, int DIN, const float* __restrict__ skipv,
    ScatJob sj, const float* __restrict__ Wc, const float* __restrict__ bc) {
    constexpr int NH = NCOLS / 2;
    constexpr int J2N = NH / 16;
    constexpr int JN = NH / 8;
    constexpr int BSTR = NCOLS + 8;
    constexpr int A_SPLIT_B = 128 * AS_STRIDE * 2;
    constexpr int A_STAGE_B = 2 * A_SPLIT_B;
    constexpr int B_SPLIT_B = 32 * BSTR * 2;
    constexpr int B_STAGE_B = 2 * B_SPLIT_B;
    extern __shared__ __align__(16) char dsmem[];
    __shared__ float sred[FINAL ? 128 : 1];

    int t = threadIdx.x;
    if (SCAT) {
        if (blockIdx.x < (unsigned)sj.nblocks) {
            int e = blockIdx.x * 256 + t;
            if (e < sj.E0) {
                int p = atomicAdd(&sj.cur0[sj.d0[e]], 1);
                sj.out0[p] = sj.s0[e];
            } else if (e < sj.E0 + sj.E1) {
                int ee = e - sj.E0;
                int p = atomicAdd(&sj.cur1[sj.d1[ee]], 1);
                sj.out1[p] = sj.s1[ee];
            }
            return;
        }
    }
    int bx = blockIdx.x - (SCAT ? sj.nblocks : 0);
    bool second = bx >= nb0;
    GemmJob J = second ? j1 : j0;
    int b = second ? bx - nb0 : bx;
    int rb, cb;
    if (J.colBlocks == 2) { rb = b >> 1; cb = b & 1; } else { rb = b; cb = 0; }
    int row0 = rb * 128;
    int colW = J.col0 + cb * NCOLS;

    int w = t >> 5, lane = t & 31;
    int mbase = (w >> 1) * 32;
    int nbase = (w & 1) * NH;
    int lrow = lane & 15;
    int lcolo = (lane >> 4) * 8;

    uint32_t sbase = (uint32_t)__cvta_generic_to_shared(dsmem);
    uint32_t aS = sbase;
    uint32_t bS = sbase + 2 * A_STAGE_B;

    auto stage_chunk = [&](int kc, int s) {
        #pragma unroll
        for (int ii = 0; ii < 4; ii++) {
            int idx = t + ii * 256;       // 0..1023 : 2 splits x 512 granules
            int sp = idx >> 9, g = idx & 511;
            int r = g >> 2, q = g & 3;
            int grow = row0 + r;
            int ok = grow < J.N;
            const bf16* gp = (sp ? J.Al : J.Ah) + (size_t)(ok ? grow : 0) * J.lda + kc + q * 8;
            cp16(aS + s * A_STAGE_B + sp * A_SPLIT_B + (r * AS_STRIDE + q * 8) * 2, gp, ok ? 16 : 0);
        }
        constexpr int BG = 32 * (NCOLS / 8);
        #pragma unroll
        for (int ii = 0; ii < (2 * BG + 255) / 256; ii++) {
            int idx = t + ii * 256;
            if (idx < 2 * BG) {
                int sp = idx >= BG;
                int g = idx - (sp ? BG : 0);
                int r = g / (NCOLS / 8), q = g % (NCOLS / 8);
                const bf16* gp = (sp ? J.Bl : J.Bh) + (size_t)(kc + r) * J.ldb + colW + q * 8;
                cp16(bS + s * B_STAGE_B + sp * B_SPLIT_B + (r * BSTR + q * 8) * 2, gp, 16);
            }
        }
    };

    float acc[2][JN][4];
    #pragma unroll
    for (int i = 0; i < 2; i++)
        #pragma unroll
        for (int j = 0; j < JN; j++)
            #pragma unroll
            for (int q = 0; q < 4; q++) acc[i][j][q] = 0.f;

    int NC = DIN / 32;
    stage_chunk(0, 0);
    CP_COMMIT();

    for (int n = 0; n < NC; n++) {
        int cur = n & 1;
        if (n + 1 < NC) {
            stage_chunk((n + 1) * 32, cur ^ 1);
            CP_COMMIT();
            CP_WAIT(1);
        } else {
            CP_WAIT(0);
        }
        __syncthreads();

        uint32_t a_base0 = aS + cur * A_STAGE_B;
        uint32_t a_base1 = a_base0 + A_SPLIT_B;
        uint32_t b_base0 = bS + cur * B_STAGE_B;
        uint32_t b_base1 = b_base0 + B_SPLIT_B;

        #pragma unroll
        for (int kb = 0; kb < 32; kb += 16) {
            uint32_t ah[2][4], al[2][4];
            #pragma unroll
            for (int i = 0; i < 2; i++) {
                uint32_t off = (uint32_t)(((mbase + i * 16 + lrow) * AS_STRIDE + kb + lcolo) * 2);
                ldsm_x4(ah[i], a_base0 + off);
                ldsm_x4(al[i], a_base1 + off);
            }
            #pragma unroll
            for (int j2 = 0; j2 < J2N; j2++) {
                uint32_t bh[4], bl[4];
                uint32_t off = (uint32_t)(((kb + lrow) * BSTR + nbase + j2 * 16 + lcolo) * 2);
                ldsm_x4_t(bh, b_base0 + off);
                ldsm_x4_t(bl, b_base1 + off);
                #pragma unroll
                for (int i = 0; i < 2; i++)
                    #pragma unroll
                    for (int jj = 0; jj < 2; jj++) {
                        int j = j2 * 2 + jj, o = jj * 2;
                        mma_bf16(acc[i][j], ah[i], bh[o], bh[o + 1]);
                        mma_bf16(acc[i][j], ah[i], bl[o], bl[o + 1]);
                        mma_bf16(acc[i][j], al[i], bh[o], bh[o + 1]);
                    }
            }
        }
        __syncthreads();
    }

    // epilogue
    int g = lane >> 2, tq = lane & 3;
    float amix = 0.f;
    if (POST == 2) amix = 1.f / (1.f + __expf(-skipv[0]));
    float fpart[2][2];
    if (FINAL) { fpart[0][0] = fpart[0][1] = fpart[1][0] = fpart[1][1] = 0.f; }
    #pragma unroll
    for (int i = 0; i < 2; i++) {
        #pragma unroll
        for (int j = 0; j < JN; j++) {
            int colg = colW + nbase + j * 8 + tq * 2;
            float b0 = J.bias[colg], b1 = J.bias[colg + 1];
            #pragma unroll
            for (int half = 0; half < 2; half++) {
                int row = row0 + mbase + i * 16 + g + half * 8;
                if (row < J.N) {
                    float o0 = acc[i][j][half * 2 + 0] + b0;
                    float o1 = acc[i][j][half * 2 + 1] + b1;
                    if (POST == 1) { o0 = fmaxf(o0, 0.f); o1 = fmaxf(o1, 0.f); }
                    if (POST == 2) {
                        o0 = amix * o0 + (1.f - amix) * J.x_in[(size_t)row * 64 + colg];
                        o1 = amix * o1 + (1.f - amix) * J.x_in[(size_t)row * 64 + colg + 1];
                    }
                    if (FINAL) {
                        fpart[i][half] += o0 * Wc[colg] + o1 * Wc[colg + 1];
                    } else if (J.outH != nullptr && colg >= 64) {
                        __half2 hv = __floats2half2_rn(o0, o1);
                        *(__half2*)(J.outH + (size_t)row * 128 + (colg - 64)) = hv;
                    } else {
                        if (J.outF)
                            *(float2*)(J.outF + (size_t)row * J.ldo + colg) = make_float2(o0, o1);
                        if (J.outBh) {
                            uint32_t hv, lv;
                            split2(o0, o1, hv, lv);
                            *(uint32_t*)(J.outBh + (size_t)row * 64 + colg) = hv;
                            *(uint32_t*)(J.outBl + (size_t)row * 64 + colg) = lv;
                        }
                    }
                }
            }
        }
    }
    if (FINAL) {
        #pragma unroll
        for (int i = 0; i < 2; i++)
            #pragma unroll
            for (int half = 0; half < 2; half++) {
                float pv = fpart[i][half];
                pv += __shfl_xor_sync(0xffffffffu, pv, 1);
                pv += __shfl_xor_sync(0xffffffffu, pv, 2);
                fpart[i][half] = pv;
            }
        if ((w & 1) == 0 && tq == 0) {
            #pragma unroll
            for (int i = 0; i < 2; i++)
                #pragma unroll
                for (int half = 0; half < 2; half++)
                    sred[mbase + i * 16 + g + half * 8] = fpart[i][half];
        }
        __syncthreads();
        if ((w & 1) == 1 && tq == 0) {
            #pragma unroll
            for (int i = 0; i < 2; i++)
                #pragma unroll
                for (int half = 0; half < 2; half++) {
                    int local = mbase + i * 16 + g + half * 8;
                    int row = row0 + local;
                    if (row < J.N)
                        J.outF[row] = sred[local] + fpart[i][half] + bc[0];
                }
        }
    }
}

// ---------------- attention: writes gelu(agg) pre-split bf16 ----------------
struct AttnSet {
    const __half* kv; const float* q;
    const int* rp; const int* srcs;
    const float* prel; bf16* aggh; bf16* aggl; int n;
};

__global__ __launch_bounds__(256) void attn_kernel(AttnSet s0, AttnSet s1) {
    int w = threadIdx.x >> 5, lane = threadIdx.x & 31;
    int d = blockIdx.x * 8 + w;
    AttnSet S;
    int dst;
    if (d < s0.n) { S = s0; dst = d; }
    else {
        dst = d - s0.n;
        if (dst >= s1.n) return;
        S = s1;
    }
    int sub = lane & 7;
    int eg = lane >> 3;
    const float* qd = S.q + (size_t)dst * 64 + sub * 8;
    float4 q0 = *(const float4*)(qd);
    float4 q1 = *(const float4*)(qd + 4);
    float pr = S.prel[sub >> 1] * 0.25f;
    float4 a0 = make_float4(0.f, 0.f, 0.f, 0.f);
    float4 a1 = make_float4(0.f, 0.f, 0.f, 0.f);
    float den = 0.f;
    int beg = S.rp[dst], end = S.rp[dst + 1];
    for (int i = beg; i < end; i += 4) {
        int ei = i + eg;
        bool valid = ei < end;
        int s = S.srcs[valid ? ei : beg];
        const __half* ps = S.kv + (size_t)s * 128 + sub * 8;
        uint4 kraw = *(const uint4*)(ps);
        uint4 vraw = *(const uint4*)(ps + 64);
        float2 k0 = __half22float2(*(__half2*)&kraw.x);
        float2 k1 = __half22float2(*(__half2*)&kraw.y);
        float2 k2 = __half22float2(*(__half2*)&kraw.z);
        float2 k3 = __half22float2(*(__half2*)&kraw.w);
        float part = q0.x * k0.x + q0.y * k0.y + q0.z * k1.x + q0.w * k1.y
                   + q1.x * k2.x + q1.y * k2.y + q1.z * k3.x + q1.w * k3.y;
        part += __shfl_xor_sync(0xffffffffu, part, 1);
        float e = valid ? __expf(part * pr) : 0.f;
        float2 v0 = __half22float2(*(__half2*)&vraw.x);
        float2 v1 = __half22float2(*(__half2*)&vraw.y);
        float2 v2 = __half22float2(*(__half2*)&vraw.z);
        float2 v3 = __half22float2(*(__half2*)&vraw.w);
        a0.x = fmaf(e, v0.x, a0.x); a0.y = fmaf(e, v0.y, a0.y);
        a0.z = fmaf(e, v1.x, a0.z); a0.w = fmaf(e, v1.y, a0.w);
        a1.x = fmaf(e, v2.x, a1.x); a1.y = fmaf(e, v2.y, a1.y);
        a1.z = fmaf(e, v3.x, a1.z); a1.w = fmaf(e, v3.y, a1.w);
        den += e;
    }
    #pragma unroll
    for (int off = 8; off <= 16; off <<= 1) {
        a0.x += __shfl_xor_sync(0xffffffffu, a0.x, off);
        a0.y += __shfl_xor_sync(0xffffffffu, a0.y, off);
        a0.z += __shfl_xor_sync(0xffffffffu, a0.z, off);
        a0.w += __shfl_xor_sync(0xffffffffu, a0.w, off);
        a1.x += __shfl_xor_sync(0xffffffffu, a1.x, off);
        a1.y += __shfl_xor_sync(0xffffffffu, a1.y, off);
        a1.z += __shfl_xor_sync(0xffffffffu, a1.z, off);
        a1.w += __shfl_xor_sync(0xffffffffu, a1.w, off);
        den  += __shfl_xor_sync(0xffffffffu, den, off);
    }
    if (lane < 8) {
        float inv = 1.f / (den + 1e-16f);
        float v[8] = { a0.x * inv, a0.y * inv, a0.z * inv, a0.w * inv,
                       a1.x * inv, a1.y * inv, a1.z * inv, a1.w * inv };
        uint32_t hh[4], ll[4];
        #pragma unroll
        for (int i2 = 0; i2 < 4; i2++) {
            float g0 = gelu_exact(v[2 * i2]);
            float g1 = gelu_exact(v[2 * i2 + 1]);
            split2(g0, g1, hh[i2], ll[i2]);
        }
        *(uint4*)(S.aggh + (size_t)dst * 64 + sub * 8) = make_uint4(hh[0], hh[1], hh[2], hh[3]);
        *(uint4*)(S.aggl + (size_t)dst * 64 + sub * 8) = make_uint4(ll[0], ll[1], ll[2], ll[3]);
    }
}

// ---------------- launch ----------------
extern "C" void kernel_launch(void* const* d_in, const int* in_sizes, int n_in,
                              void* d_out, int out_size) {
    (void)n_in; (void)out_size;
    int ebase, wbase;
    if (in_sizes[2] > 100000) { ebase = 2;  wbase = 6; }
    else                      { ebase = 27; wbase = 2; }

    const float* x_tx = (const float*)d_in[0];
    const float* x_m  = (const float*)d_in[1];
    const int* tm_src = (const int*)d_in[ebase + 0];
    const int* tm_dst = (const int*)d_in[ebase + 1];
    const int* mt_src = (const int*)d_in[ebase + 2];
    const int* mt_dst = (const int*)d_in[ebase + 3];

    const float* c1_Wk    = (const float*)d_in[wbase + 0];
    const float* c1_bk    = (const float*)d_in[wbase + 1];
    const float* c1_Wq    = (const float*)d_in[wbase + 2];
    const float* c1_bq    = (const float*)d_in[wbase + 3];
    const float* c1_Wv    = (const float*)d_in[wbase + 4];
    const float* c1_bv    = (const float*)d_in[wbase + 5];
    const float* c1_a_rel = (const float*)d_in[wbase + 6];
    const float* c1_m_rel = (const float*)d_in[wbase + 7];
    const float* c1_p_rel = (const float*)d_in[wbase + 8];
    const float* c1_Wa    = (const float*)d_in[wbase + 9];
    const float* c1_ba    = (const float*)d_in[wbase + 10];
    const float* c2_Wk    = (const float*)d_in[wbase + 11];
    const float* c2_bk    = (const float*)d_in[wbase + 12];
    const float* c2_Wq    = (const float*)d_in[wbase + 13];
    const float* c2_bq    = (const float*)d_in[wbase + 14];
    const float* c2_Wv    = (const float*)d_in[wbase + 15];
    const float* c2_bv    = (const float*)d_in[wbase + 16];
    const float* c2_a_rel = (const float*)d_in[wbase + 17];
    const float* c2_m_rel = (const float*)d_in[wbase + 18];
    const float* c2_p_rel = (const float*)d_in[wbase + 19];
    const float* c2_Wa    = (const float*)d_in[wbase + 20];
    const float* c2_ba    = (const float*)d_in[wbase + 21];
    const float* c2_skip  = (const float*)d_in[wbase + 22];
    const float* Wc       = (const float*)d_in[wbase + 23];
    const float* bc       = (const float*)d_in[wbase + 24];

    int N_TX = in_sizes[0] / 128;
    int N_M  = in_sizes[1] / 128;
    int E0 = in_sizes[ebase + 1];
    int E1 = in_sizes[ebase + 3];

    void* p;
    float *q_tx, *q_m, *h_tx, *bA1, *bB1, *bA2, *bB2;
    __half *kv_tx, *kv_m;
    bf16 *xh_tx, *xl_tx, *xh_m, *xl_m;
    bf16 *aggh_tx, *aggl_tx, *aggh_m, *aggl_m;
    bf16 *hh_tx, *hl_tx, *hh_m, *hl_m;
    bf16 *Wh1A, *Wl1A, *Wh1B, *Wl1B, *Wh2A, *Wl2A, *Wh2B, *Wl2B, *WaH, *WaL;
    int *rowptr0, *rowptr1, *cursor0, *cursor1, *srcs0, *srcs1;
    cudaGetSymbolAddress(&p, g_q_tx);    q_tx    = (float*)p;
    cudaGetSymbolAddress(&p, g_q_m);     q_m     = (float*)p;
    cudaGetSymbolAddress(&p, g_kv_tx);   kv_tx   = (__half*)p;
    cudaGetSymbolAddress(&p, g_kv_m);    kv_m    = (__half*)p;
    cudaGetSymbolAddress(&p, g_h_tx);    h_tx    = (float*)p;
    cudaGetSymbolAddress(&p, g_xh_tx);   xh_tx   = (bf16*)p;
    cudaGetSymbolAddress(&p, g_xl_tx);   xl_tx   = (bf16*)p;
    cudaGetSymbolAddress(&p, g_xh_m);    xh_m    = (bf16*)p;
    cudaGetSymbolAddress(&p, g_xl_m);    xl_m    = (bf16*)p;
    cudaGetSymbolAddress(&p, g_aggh_tx); aggh_tx = (bf16*)p;
    cudaGetSymbolAddress(&p, g_aggl_tx); aggl_tx = (bf16*)p;
    cudaGetSymbolAddress(&p, g_aggh_m);  aggh_m  = (bf16*)p;
    cudaGetSymbolAddress(&p, g_aggl_m);  aggl_m  = (bf16*)p;
    cudaGetSymbolAddress(&p, g_hh_tx);   hh_tx   = (bf16*)p;
    cudaGetSymbolAddress(&p, g_hl_tx);   hl_tx   = (bf16*)p;
    cudaGetSymbolAddress(&p, g_hh_m);    hh_m    = (bf16*)p;
    cudaGetSymbolAddress(&p, g_hl_m);    hl_m    = (bf16*)p;
    cudaGetSymbolAddress(&p, g_Wh1A);    Wh1A    = (bf16*)p;
    cudaGetSymbolAddress(&p, g_Wl1A);    Wl1A    = (bf16*)p;
    cudaGetSymbolAddress(&p, g_Wh1B);    Wh1B    = (bf16*)p;
    cudaGetSymbolAddress(&p, g_Wl1B);    Wl1B    = (bf16*)p;
    cudaGetSymbolAddress(&p, g_Wh2A);    Wh2A    = (bf16*)p;
    cudaGetSymbolAddress(&p, g_Wl2A);    Wl2A    = (bf16*)p;
    cudaGetSymbolAddress(&p, g_Wh2B);    Wh2B    = (bf16*)p;
    cudaGetSymbolAddress(&p, g_Wl2B);    Wl2B    = (bf16*)p;
    cudaGetSymbolAddress(&p, g_WaH);     WaH     = (bf16*)p;
    cudaGetSymbolAddress(&p, g_WaL);     WaL     = (bf16*)p;
    cudaGetSymbolAddress(&p, g_bA1);     bA1     = (float*)p;
    cudaGetSymbolAddress(&p, g_bB1);     bB1     = (float*)p;
    cudaGetSymbolAddress(&p, g_bA2);     bA2     = (float*)p;
    cudaGetSymbolAddress(&p, g_bB2);     bB2     = (float*)p;
    cudaGetSymbolAddress(&p, g_rowptr0); rowptr0 = (int*)p;
    cudaGetSymbolAddress(&p, g_rowptr1); rowptr1 = (int*)p;
    cudaGetSymbolAddress(&p, g_cursor0); cursor0 = (int*)p;
    cudaGetSymbolAddress(&p, g_cursor1); cursor1 = (int*)p;
    cudaGetSymbolAddress(&p, g_srcs0);   srcs0   = (int*)p;
    cudaGetSymbolAddress(&p, g_srcs1);   srcs1   = (int*)p;

    int gbTX = (N_TX + 127) / 128;
    int gbM  = (N_M + 127) / 128;

    // dynamic smem sizes
    const int SM96 = 2 * (2 * 128 * AS_STRIDE * 2) + 2 * (2 * 32 * (96 + 8) * 2);
    const int SM64 = 2 * (2 * 128 * AS_STRIDE * 2) + 2 * (2 * 32 * (64 + 8) * 2);
    cudaFuncSetAttribute(mma_gemm_kernel<0, 96, 1, 0>, cudaFuncAttributeMaxDynamicSharedMemorySize, SM96);
    cudaFuncSetAttribute(mma_gemm_kernel<1, 64, 0, 0>, cudaFuncAttributeMaxDynamicSharedMemorySize, SM64);
    cudaFuncSetAttribute(mma_gemm_kernel<0, 64, 0, 0>, cudaFuncAttributeMaxDynamicSharedMemorySize, SM64);
    cudaFuncSetAttribute(mma_gemm_kernel<2, 64, 0, 1>, cudaFuncAttributeMaxDynamicSharedMemorySize, SM64);

    ScatJob sjNone = {};
    sjNone.nblocks = 0;

    // ---- 1: prep (weights split + Wa split + cursor zero + x split) ----
    {
        PrepJob P;
        P.Wq1 = c1_Wq; P.bq1 = c1_bq; P.Wk1 = c1_Wk; P.bk1 = c1_bk;
        P.Wv1 = c1_Wv; P.bv1 = c1_bv; P.a1 = c1_a_rel; P.m1 = c1_m_rel;
        P.Wq2 = c2_Wq; P.bq2 = c2_bq; P.Wk2 = c2_Wk; P.bk2 = c2_bk;
        P.Wv2 = c2_Wv; P.bv2 = c2_bv; P.a2 = c2_a_rel; P.m2 = c2_m_rel;
        P.Wa1 = c1_Wa; P.Wa2 = c2_Wa;
        P.x_tx = x_tx; P.x_m = x_m;
        P.Wh1A = Wh1A; P.Wl1A = Wl1A; P.Wh1B = Wh1B; P.Wl1B = Wl1B;
        P.Wh2A = Wh2A; P.Wl2A = Wl2A; P.Wh2B = Wh2B; P.Wl2B = Wl2B;
        P.bA1 = bA1; P.bB1 = bB1; P.bA2 = bA2; P.bB2 = bB2;
        P.WaH = WaH; P.WaL = WaL;
        P.xh_tx = xh_tx; P.xl_tx = xl_tx; P.xh_m = xh_m; P.xl_m = xl_m;
        P.cur0 = cursor0; P.cur1 = cursor1;
        P.nm = N_M; P.ntx = N_TX;
        int Z = (N_M + N_TX + 255) / 256;
        P.c4 = 292 + Z;
        P.c5 = P.c4 + 48;
        int X = ((N_TX + N_M) * 32 + 255) / 256;
        prep_kernel<<<P.c5 + X, 256>>>(P);
    }

    // ---- 2-3: hist + scan ----
    hist_both_kernel<<<(E0 + E1 + 255) / 256, 256>>>(tm_dst, E0, cursor0, mt_dst, E1, cursor1);
    scan_both_kernel<<<2, 1024>>>(cursor0, rowptr0, N_M, cursor1, rowptr1, N_TX);

    // ---- 4: scatter + L1 QKV GEMM fused ----
    {
        ScatJob sj = { tm_src, tm_dst, E0, cursor0, srcs0,
                       mt_src, mt_dst, E1, cursor1, srcs1,
                       (E0 + E1 + 255) / 256 };
        GemmJob j0 = { xh_tx, xl_tx, Wh1A, Wl1A, bA1, nullptr,
                       q_tx, kv_tx, nullptr, nullptr, N_TX, 128, 192, 0, 64, 2 };
        GemmJob j1 = { xh_m, xl_m, Wh1B, Wl1B, bB1, nullptr,
                       q_m, kv_m, nullptr, nullptr, N_M, 128, 192, 0, 64, 2 };
        int nb0 = gbTX * 2;
        mma_gemm_kernel<0, 96, 1, 0><<<sj.nblocks + nb0 + gbM * 2, 256, SM96>>>(
            j0, j1, nb0, 128, nullptr, sj, nullptr, nullptr);
    }

    // ---- 5: L1 attention (both directions) ----
    {
        AttnSet s0 = { kv_tx, q_m,  rowptr0, srcs0, c1_p_rel,     aggh_m,  aggl_m,  N_M };
        AttnSet s1 = { kv_m,  q_tx, rowptr1, srcs1, c1_p_rel + 4, aggh_tx, aggl_tx, N_TX };
        attn_kernel<<<(N_M + N_TX + 7) / 8, 256>>>(s0, s1);
    }

    // ---- 6: L1 epilogue (tx + m): h = relu(gelu(agg) @ Wa + ba), writes fp32 h_tx + bf16 splits ----
    {
        GemmJob j0 = { aggh_tx, aggl_tx, WaH, WaL, c1_ba, nullptr,
                       h_tx, nullptr, hh_tx, hl_tx, N_TX, 64, 64, 0, 64, 1 };
        GemmJob j1 = { aggh_m, aggl_m, WaH + 4096, WaL + 4096, c1_ba + 64, nullptr,
                       nullptr, nullptr, hh_m, hl_m, N_M, 64, 64, 0, 64, 1 };
        mma_gemm_kernel<1, 64, 0, 0><<<gbTX + gbM, 256, SM64>>>(
            j0, j1, gbTX, 64, nullptr, sjNone, nullptr, nullptr);
    }

    // ---- 7: L2 projections: tx Q + m KV ----
    {
        GemmJob j0 = { hh_tx, hl_tx, Wh2A, Wl2A, bA2, nullptr,
                       q_tx, nullptr, nullptr, nullptr, N_TX, 64, 192, 0, 64, 1 };
        GemmJob j1 = { hh_m, hl_m, Wh2B, Wl2B, bB2, nullptr,
                       nullptr, kv_m, nullptr, nullptr, N_M, 64, 192, 64, 0, 2 };
        mma_gemm_kernel<0, 64, 0, 0><<<gbTX + gbM * 2, 256, SM64>>>(
            j0, j1, gbTX, 64, nullptr, sjNone, nullptr, nullptr);
    }

    // ---- 8: L2 attention (tx dst only) ----
    {
        AttnSet s1 = { kv_m, q_tx, rowptr1, srcs1, c2_p_rel + 4, aggh_tx, aggl_tx, N_TX };
        AttnSet s0 = s1; s0.n = 0;
        attn_kernel<<<(N_TX + 7) / 8, 256>>>(s0, s1);
    }

    // ---- 9: L2 epilogue + skip mix + fused final logits -> d_out ----
    {
        GemmJob j0 = { aggh_tx, aggl_tx, WaH + 2 * 4096, WaL + 2 * 4096, c2_ba, h_tx,
                       (float*)d_out, nullptr, nullptr, nullptr, N_TX, 64, 64, 0, 1, 1 };
        mma_gemm_kernel<2, 64, 0, 1><<<gbTX, 256, SM64>>>(
            j0, j0, gbTX, 64, c2_skip, sjNone, Wc, bc);
    }
}

// round 13
// speedup vs baseline: 1.0418x; 1.0418x over previous
#include <cuda_runtime.h>
#include <cuda_bf16.h>
#include <cuda_fp16.h>
#include <cstdint>

#define NTX_MAX 100000
#define NM_MAX  20000
#define E_MAX   500000

typedef __nv_bfloat16 bf16;

// ---------------- scratch (static device globals; no runtime allocation) ----------------
__device__ float  g_q_tx [(size_t)NTX_MAX * 64];   // fp32 Q
__device__ float  g_q_m  [(size_t)NM_MAX  * 64];
__device__ __half g_kv_tx[(size_t)NTX_MAX * 128];  // fp16 [Khat | Vhat]
__device__ __half g_kv_m [(size_t)NM_MAX  * 128];
__device__ float  g_agg_tx[(size_t)NTX_MAX * 64];
__device__ float  g_agg_m [(size_t)NM_MAX  * 64];
__device__ float  g_h_tx  [(size_t)NTX_MAX * 64];
__device__ float  g_h_m   [(size_t)NM_MAX  * 64];
__device__ float  g_WA1[128 * 192];  __device__ float g_bA1[192];
__device__ float  g_WB1[128 * 192];  __device__ float g_bB1[192];
__device__ float  g_WA2[128 * 192];  __device__ float g_bA2[192];
__device__ float  g_WB2[128 * 192];  __device__ float g_bB2[192];
// CSR
__device__ int g_rowptr0[NM_MAX + 1];   // dst = m   (tx->m edges)
__device__ int g_rowptr1[NTX_MAX + 1];  // dst = tx  (m->tx edges)
__device__ int g_cursor0[NM_MAX];
__device__ int g_cursor1[NTX_MAX];
__device__ int g_srcs0[E_MAX];
__device__ int g_srcs1[E_MAX];

// ---------------- CSR build ----------------
__global__ void hist_both_kernel(const int* __restrict__ d0, int E0, int* __restrict__ c0,
                                 const int* __restrict__ d1, int E1, int* __restrict__ c1) {
    int e = blockIdx.x * blockDim.x + threadIdx.x;
    if (e < E0) atomicAdd(&c0[d0[e]], 1);
    else if (e < E0 + E1) atomicAdd(&c1[d1[e - E0]], 1);
}

__global__ void scan_both_kernel(int* __restrict__ cnt0, int* __restrict__ rp0, int n0,
                                 int* __restrict__ cnt1, int* __restrict__ rp1, int n1) {
    __shared__ int ssum[1024];
    int* cnt = blockIdx.x ? cnt1 : cnt0;
    int* rowptr = blockIdx.x ? rp1 : rp0;
    int n = blockIdx.x ? n1 : n0;
    int tid = threadIdx.x;
    int chunk = (n + 1023) / 1024;
    int start = tid * chunk;
    int end = start + chunk; if (end > n) end = n; if (start > n) start = n;
    int s = 0;
    for (int i = start; i < end; i++) s += cnt[i];
    ssum[tid] = s;
    __syncthreads();
    for (int off = 1; off < 1024; off <<= 1) {
        int v = (tid >= off) ? ssum[tid - off] : 0;
        __syncthreads();
        ssum[tid] += v;
        __syncthreads();
    }
    int run = (tid == 0) ? 0 : ssum[tid - 1];
    for (int i = start; i < end; i++) {
        int c = cnt[i];
        rowptr[i] = run;
        cnt[i] = run;       // cursor = rowptr (cnt doubles as cursor)
        run += c;
    }
    if (tid == 1023) rowptr[n] = run;
}

// ---------------- effective fused weights + CSR zeroing, one launch ----------------
// y = 0..3: eff weights (L1 tx, L1 m, L2 tx, L2 m); y = 4: zero cursor arrays.
__global__ void eff_all_kernel(
    const float* c1_Wq, const float* c1_bq, const float* c1_Wk, const float* c1_bk,
    const float* c1_Wv, const float* c1_bv, const float* c1_a, const float* c1_m,
    const float* c2_Wq, const float* c2_bq, const float* c2_Wk, const float* c2_bk,
    const float* c2_Wv, const float* c2_bv, const float* c2_a, const float* c2_m,
    float* WA1, float* bA1, float* WB1, float* bB1,
    float* WA2, float* bA2, float* WB2, float* bB2,
    int* cur0, int n0, int* cur1, int n1) {
    int y = blockIdx.y;
    int idx = blockIdx.x * blockDim.x + threadIdx.x;
    if (y == 4) {
        if (idx < n0) cur0[idx] = 0;
        else if (idx < n0 + n1) cur1[idx - n0] = 0;
        return;
    }
    int layer = y >> 1, typ = y & 1;
    int din = layer ? 64 : 128;
    int total = (din + 1) * 192;
    if (idx >= total) return;
    const float* Wq = layer ? c2_Wq : c1_Wq;  const float* bq = layer ? c2_bq : c1_bq;
    const float* Wk = layer ? c2_Wk : c1_Wk;  const float* bk = layer ? c2_bk : c1_bk;
    const float* Wv = layer ? c2_Wv : c1_Wv;  const float* bv = layer ? c2_bv : c1_bv;
    const float* ar = layer ? c2_a : c1_a;    const float* mr = layer ? c2_m : c1_m;
    Wq += (size_t)typ * din * 64; bq += typ * 64;
    Wk += (size_t)typ * din * 64; bk += typ * 64;
    Wv += (size_t)typ * din * 64; bv += typ * 64;
    ar += typ * 1024; mr += typ * 1024;
    float* Wout = layer ? (typ ? WB2 : WA2) : (typ ? WB1 : WA1);
    float* bout = layer ? (typ ? bB2 : bA2) : (typ ? bB1 : bA1);

    int i = idx / 192, c = idx % 192;
    bool isBias = (i == din);
    float val;
    if (c < 64) {
        val = isBias ? bq[c] : Wq[i * 64 + c];
    } else {
        int cc = c - 64;
        bool isV = (cc >= 64);
        if (isV) cc -= 64;
        int h = cc >> 4, e = cc & 15;
        const float* rel  = isV ? mr : ar;
        const float* Wsrc = isV ? Wv : Wk;
        const float* bsrc = isV ? bv : bk;
        float s = 0.f;
        #pragma unroll
        for (int d = 0; d < 16; d++) {
            float w = isBias ? bsrc[h * 16 + d] : Wsrc[i * 64 + h * 16 + d];
            s += w * rel[h * 256 + d * 16 + e];
        }
        val = s;
    }
    if (isBias) bout[c] = val;
    else        Wout[i * 192 + c] = val;
}

// ---------------- tensor-core GEMM (fused fp32->bf16 3-split, fp32 accumulate) ----------------
__device__ __forceinline__ void ldsm_x4(uint32_t* r, uint32_t addr) {
    asm volatile("ldmatrix.sync.aligned.m8n8.x4.shared.b16 {%0,%1,%2,%3}, [%4];"
        : "=r"(r[0]), "=r"(r[1]), "=r"(r[2]), "=r"(r[3]) : "r"(addr));
}
__device__ __forceinline__ void ldsm_x4_t(uint32_t* r, uint32_t addr) {
    asm volatile("ldmatrix.sync.aligned.m8n8.x4.trans.shared.b16 {%0,%1,%2,%3}, [%4];"
        : "=r"(r[0]), "=r"(r[1]), "=r"(r[2]), "=r"(r[3]) : "r"(addr));
}
__device__ __forceinline__ void mma_bf16(float* c, const uint32_t* a, uint32_t b0, uint32_t b1) {
    asm volatile("mma.sync.aligned.m16n8k16.row.col.f32.bf16.bf16.f32 "
        "{%0,%1,%2,%3}, {%4,%5,%6,%7}, {%8,%9}, {%0,%1,%2,%3};"
        : "+f"(c[0]), "+f"(c[1]), "+f"(c[2]), "+f"(c[3])
        : "r"(a[0]), "r"(a[1]), "r"(a[2]), "r"(a[3]), "r"(b0), "r"(b1));
}

__device__ __forceinline__ void split2(float x, float y, uint32_t& hi, uint32_t& lo) {
    bf16 hx = __float2bfloat16_rn(x), hy = __float2bfloat16_rn(y);
    bf16 lx = __float2bfloat16_rn(x - __bfloat162float(hx));
    bf16 ly = __float2bfloat16_rn(y - __bfloat162float(hy));
    __nv_bfloat162 h2 = __halves2bfloat162(hx, hy);
    __nv_bfloat162 l2 = __halves2bfloat162(lx, ly);
    hi = *(uint32_t*)&h2;
    lo = *(uint32_t*)&l2;
}

__device__ __forceinline__ float gelu_exact(float v) {
    return 0.5f * v * (1.f + erff(v * 0.70710678118654752f));
}

#define AS_STRIDE 40   // 32 + 8 pad (bf16 elems): conflict-free ldmatrix

struct GemmJob {
    const float* A; const float* B; const float* bias; const float* x_in;
    float* outF; __half* outH;
    int N, ldb, col0, ldo, colBlocks;
};

struct ScatJob {
    const int* s0; const int* d0; int E0; int* cur0; int* out0;
    const int* s1; const int* d1; int E1; int* cur1; int* out1;
    int nblocks;
};

// POST: 0 = bias only, 1 = bias+relu, 2 = bias + skip-mix.  AGELU: gelu(A) while staging.
// ROWS x NCOLS output tile per block, 8 warps of 32 x (NCOLS/(8/(ROWS/32))).
// SCAT: first sj.nblocks blocks perform the CSR scatter instead of GEMM work.
// FINAL: fuse logits (out[row] = sum_c o[row][c]*Wc[c] + bc) — requires ROWS=128/NCOLS=64.
// fp16 KV epilogue: any colg >= 64 with outH set goes to outH (ld 128, offset -64).
template <int POST, int AGELU, int ROWS, int NCOLS, int SCAT, int FINAL>
__global__ __launch_bounds__(256) void mma_gemm_kernel(
    GemmJob j0, GemmJob j1, int nb0, int DIN, const float* __restrict__ skipv,
    ScatJob sj, const float* __restrict__ Wc, const float* __restrict__ bc) {
    constexpr int MW  = ROWS / 32;       // warp m-groups
    constexpr int NWN = 8 / MW;          // warp n-groups
    constexpr int NH  = NCOLS / NWN;     // warp n-width
    constexpr int J2N = NH / 16;         // ldsm_t groups per warp
    constexpr int JN  = NH / 8;          // mma-n groups per warp
    constexpr int BSTR = NCOLS + 8;
    constexpr int BQ = NCOLS / 4;        // float4 per B row
    constexpr int NB = NCOLS / 32;       // B staging rounds
    constexpr int AIT = ROWS / 32;       // A staging rounds
    __shared__ bf16 As[2][ROWS * AS_STRIDE];
    __shared__ bf16 Bs[2][32 * BSTR];
    __shared__ float sred[FINAL ? 128 : 1];

    int t = threadIdx.x;
    if (SCAT) {
        if (blockIdx.x < (unsigned)sj.nblocks) {
            int e = blockIdx.x * 256 + t;
            if (e < sj.E0) {
                int p = atomicAdd(&sj.cur0[sj.d0[e]], 1);
                sj.out0[p] = sj.s0[e];
            } else if (e < sj.E0 + sj.E1) {
                int ee = e - sj.E0;
                int p = atomicAdd(&sj.cur1[sj.d1[ee]], 1);
                sj.out1[p] = sj.s1[ee];
            }
            return;
        }
    }
    int bx = blockIdx.x - (SCAT ? sj.nblocks : 0);
    bool second = bx >= nb0;
    GemmJob J = second ? j1 : j0;
    int b = second ? bx - nb0 : bx;
    int rb, cb;
    if (J.colBlocks == 2) { rb = b >> 1; cb = b & 1; } else { rb = b; cb = 0; }
    int row0 = rb * ROWS;
    int colW = J.col0 + cb * NCOLS;

    int w = t >> 5, lane = t & 31;
    int mbase = (w / NWN) * 32;
    int nbase = (w % NWN) * NH;
    int lrow = lane & 15;
    int lcolo = (lane >> 4) * 8;

    uint32_t a_base0 = (uint32_t)__cvta_generic_to_shared(&As[0][0]);
    uint32_t a_base1 = (uint32_t)__cvta_generic_to_shared(&As[1][0]);
    uint32_t b_base0 = (uint32_t)__cvta_generic_to_shared(&Bs[0][0]);
    uint32_t b_base1 = (uint32_t)__cvta_generic_to_shared(&Bs[1][0]);

    float acc[2][JN][4];
    #pragma unroll
    for (int i = 0; i < 2; i++)
        #pragma unroll
        for (int j = 0; j < JN; j++)
            #pragma unroll
            for (int q = 0; q < 4; q++) acc[i][j][q] = 0.f;

    for (int k0 = 0; k0 < DIN; k0 += 32) {
        // stage A: ROWS x 32 fp32 -> hi/lo bf16 (optional gelu)
        #pragma unroll
        for (int ii = 0; ii < AIT; ii++) {
            int idx = t + ii * 256;
            int r = idx >> 3, q = idx & 7;
            int grow = row0 + r;
            float4 v = make_float4(0.f, 0.f, 0.f, 0.f);
            if (grow < J.N) v = *(const float4*)(J.A + (size_t)grow * DIN + k0 + q * 4);
            if (AGELU) {
                v.x = gelu_exact(v.x); v.y = gelu_exact(v.y);
                v.z = gelu_exact(v.z); v.w = gelu_exact(v.w);
            }
            uint32_t h0, l0, h1, l1;
            split2(v.x, v.y, h0, l0);
            split2(v.z, v.w, h1, l1);
            *(uint2*)(&As[0][r * AS_STRIDE + q * 4]) = make_uint2(h0, h1);
            *(uint2*)(&As[1][r * AS_STRIDE + q * 4]) = make_uint2(l0, l1);
        }
        // stage B: 32 rows x NCOLS fp32 -> hi/lo bf16
        #pragma unroll
        for (int ii = 0; ii < NB; ii++) {
            int idx = t + ii * 256;
            int r = idx / BQ, q = idx % BQ;
            float4 v = *(const float4*)(J.B + (size_t)(k0 + r) * J.ldb + colW + q * 4);
            uint32_t h0, l0, h1, l1;
            split2(v.x, v.y, h0, l0);
            split2(v.z, v.w, h1, l1);
            *(uint2*)(&Bs[0][r * BSTR + q * 4]) = make_uint2(h0, h1);
            *(uint2*)(&Bs[1][r * BSTR + q * 4]) = make_uint2(l0, l1);
        }
        __syncthreads();

        #pragma unroll
        for (int kb = 0; kb < 32; kb += 16) {
            uint32_t ah[2][4], al[2][4];
            #pragma unroll
            for (int i = 0; i < 2; i++) {
                uint32_t off = (uint32_t)(((mbase + i * 16 + lrow) * AS_STRIDE + kb + lcolo) * 2);
                ldsm_x4(ah[i], a_base0 + off);
                ldsm_x4(al[i], a_base1 + off);
            }
            #pragma unroll
            for (int j2 = 0; j2 < J2N; j2++) {
                uint32_t bh[4], bl[4];
                uint32_t off = (uint32_t)(((kb + lrow) * BSTR + nbase + j2 * 16 + lcolo) * 2);
                ldsm_x4_t(bh, b_base0 + off);
                ldsm_x4_t(bl, b_base1 + off);
                #pragma unroll
                for (int i = 0; i < 2; i++)
                    #pragma unroll
                    for (int jj = 0; jj < 2; jj++) {
                        int j = j2 * 2 + jj, o = jj * 2;
                        mma_bf16(acc[i][j], ah[i], bh[o], bh[o + 1]);
                        mma_bf16(acc[i][j], ah[i], bl[o], bl[o + 1]);
                        mma_bf16(acc[i][j], al[i], bh[o], bh[o + 1]);
                    }
            }
        }
        __syncthreads();
    }

    // epilogue
    int g = lane >> 2, tq = lane & 3;
    float amix = 0.f;
    if (POST == 2) amix = 1.f / (1.f + __expf(-skipv[0]));
    float fpart[2][2];
    if (FINAL) { fpart[0][0] = fpart[0][1] = fpart[1][0] = fpart[1][1] = 0.f; }
    #pragma unroll
    for (int i = 0; i < 2; i++) {
        #pragma unroll
        for (int j = 0; j < JN; j++) {
            int colg = colW + nbase + j * 8 + tq * 2;
            float b0 = J.bias[colg], b1 = J.bias[colg + 1];
            #pragma unroll
            for (int half = 0; half < 2; half++) {
                int row = row0 + mbase + i * 16 + g + half * 8;
                if (row < J.N) {
                    float o0 = acc[i][j][half * 2 + 0] + b0;
                    float o1 = acc[i][j][half * 2 + 1] + b1;
                    if (POST == 1) { o0 = fmaxf(o0, 0.f); o1 = fmaxf(o1, 0.f); }
                    if (POST == 2) {
                        o0 = amix * o0 + (1.f - amix) * J.x_in[(size_t)row * 64 + colg];
                        o1 = amix * o1 + (1.f - amix) * J.x_in[(size_t)row * 64 + colg + 1];
                    }
                    if (FINAL) {
                        fpart[i][half] += o0 * Wc[colg] + o1 * Wc[colg + 1];
                    } else if (J.outH != nullptr && colg >= 64) {
                        __half2 hv = __floats2half2_rn(o0, o1);
                        *(__half2*)(J.outH + (size_t)row * 128 + (colg - 64)) = hv;
                    } else {
                        *(float2*)(J.outF + (size_t)row * J.ldo + colg) = make_float2(o0, o1);
                    }
                }
            }
        }
    }
    if (FINAL) {
        #pragma unroll
        for (int i = 0; i < 2; i++)
            #pragma unroll
            for (int half = 0; half < 2; half++) {
                float pv = fpart[i][half];
                pv += __shfl_xor_sync(0xffffffffu, pv, 1);
                pv += __shfl_xor_sync(0xffffffffu, pv, 2);
                fpart[i][half] = pv;
            }
        if ((w & 1) == 0 && tq == 0) {
            #pragma unroll
            for (int i = 0; i < 2; i++)
                #pragma unroll
                for (int half = 0; half < 2; half++)
                    sred[mbase + i * 16 + g + half * 8] = fpart[i][half];
        }
        __syncthreads();
        if ((w & 1) == 1 && tq == 0) {
            #pragma unroll
            for (int i = 0; i < 2; i++)
                #pragma unroll
                for (int half = 0; half < 2; half++) {
                    int local = mbase + i * 16 + g + half * 8;
                    int row = row0 + local;
                    if (row < J.N)
                        J.outF[row] = sred[local] + fpart[i][half] + bc[0];
                }
        }
    }
}

// ---------------- attention (merged over both dst sets) ----------------
struct AttnSet {
    const __half* kv; const float* q;
    const int* rp; const int* srcs;
    const float* prel; float* agg; int n;
};

__global__ __launch_bounds__(256) void attn_kernel(AttnSet s0, AttnSet s1) {
    int w = threadIdx.x >> 5, lane = threadIdx.x & 31;
    int d = blockIdx.x * 8 + w;
    AttnSet S;
    int dst;
    if (d < s0.n) { S = s0; dst = d; }
    else {
        dst = d - s0.n;
        if (dst >= s1.n) return;
        S = s1;
    }
    int sub = lane & 7;
    int eg = lane >> 3;
    const float* qd = S.q + (size_t)dst * 64 + sub * 8;
    float4 q0 = *(const float4*)(qd);
    float4 q1 = *(const float4*)(qd + 4);
    float pr = S.prel[sub >> 1] * 0.25f;   // /SQRT_D folded
    float4 a0 = make_float4(0.f, 0.f, 0.f, 0.f);
    float4 a1 = make_float4(0.f, 0.f, 0.f, 0.f);
    float den = 0.f;
    int beg = S.rp[dst], end = S.rp[dst + 1];
    for (int i = beg; i < end; i += 4) {
        int ei = i + eg;
        bool valid = ei < end;
        int s = S.srcs[valid ? ei : beg];
        const __half* ps = S.kv + (size_t)s * 128 + sub * 8;
        uint4 kraw = *(const uint4*)(ps);        // 8 halfs: K slice
        uint4 vraw = *(const uint4*)(ps + 64);   // 8 halfs: V slice
        float2 k0 = __half22float2(*(__half2*)&kraw.x);
        float2 k1 = __half22float2(*(__half2*)&kraw.y);
        float2 k2 = __half22float2(*(__half2*)&kraw.z);
        float2 k3 = __half22float2(*(__half2*)&kraw.w);
        float part = q0.x * k0.x + q0.y * k0.y + q0.z * k1.x + q0.w * k1.y
                   + q1.x * k2.x + q1.y * k2.y + q1.z * k3.x + q1.w * k3.y;
        part += __shfl_xor_sync(0xffffffffu, part, 1);
        float e = valid ? __expf(part * pr) : 0.f;
        float2 v0 = __half22float2(*(__half2*)&vraw.x);
        float2 v1 = __half22float2(*(__half2*)&vraw.y);
        float2 v2 = __half22float2(*(__half2*)&vraw.z);
        float2 v3 = __half22float2(*(__half2*)&vraw.w);
        a0.x = fmaf(e, v0.x, a0.x); a0.y = fmaf(e, v0.y, a0.y);
        a0.z = fmaf(e, v1.x, a0.z); a0.w = fmaf(e, v1.y, a0.w);
        a1.x = fmaf(e, v2.x, a1.x); a1.y = fmaf(e, v2.y, a1.y);
        a1.z = fmaf(e, v3.x, a1.z); a1.w = fmaf(e, v3.y, a1.w);
        den += e;
    }
    #pragma unroll
    for (int off = 8; off <= 16; off <<= 1) {
        a0.x += __shfl_xor_sync(0xffffffffu, a0.x, off);
        a0.y += __shfl_xor_sync(0xffffffffu, a0.y, off);
        a0.z += __shfl_xor_sync(0xffffffffu, a0.z, off);
        a0.w += __shfl_xor_sync(0xffffffffu, a0.w, off);
        a1.x += __shfl_xor_sync(0xffffffffu, a1.x, off);
        a1.y += __shfl_xor_sync(0xffffffffu, a1.y, off);
        a1.z += __shfl_xor_sync(0xffffffffu, a1.z, off);
        a1.w += __shfl_xor_sync(0xffffffffu, a1.w, off);
        den  += __shfl_xor_sync(0xffffffffu, den, off);
    }
    if (lane < 8) {
        float inv = 1.f / (den + 1e-16f);
        a0.x *= inv; a0.y *= inv; a0.z *= inv; a0.w *= inv;
        a1.x *= inv; a1.y *= inv; a1.z *= inv; a1.w *= inv;
        float* op = S.agg + (size_t)dst * 64 + sub * 8;
        *(float4*)(op) = a0;
        *(float4*)(op + 4) = a1;
    }
}

// ---------------- launch ----------------
extern "C" void kernel_launch(void* const* d_in, const int* in_sizes, int n_in,
                              void* d_out, int out_size) {
    (void)n_in; (void)out_size;
    int ebase, wbase;
    if (in_sizes[2] > 100000) { ebase = 2;  wbase = 6; }
    else                      { ebase = 27; wbase = 2; }

    const float* x_tx = (const float*)d_in[0];
    const float* x_m  = (const float*)d_in[1];
    const int* tm_src = (const int*)d_in[ebase + 0];
    const int* tm_dst = (const int*)d_in[ebase + 1];
    const int* mt_src = (const int*)d_in[ebase + 2];
    const int* mt_dst = (const int*)d_in[ebase + 3];

    const float* c1_Wk    = (const float*)d_in[wbase + 0];
    const float* c1_bk    = (const float*)d_in[wbase + 1];
    const float* c1_Wq    = (const float*)d_in[wbase + 2];
    const float* c1_bq    = (const float*)d_in[wbase + 3];
    const float* c1_Wv    = (const float*)d_in[wbase + 4];
    const float* c1_bv    = (const float*)d_in[wbase + 5];
    const float* c1_a_rel = (const float*)d_in[wbase + 6];
    const float* c1_m_rel = (const float*)d_in[wbase + 7];
    const float* c1_p_rel = (const float*)d_in[wbase + 8];
    const float* c1_Wa    = (const float*)d_in[wbase + 9];
    const float* c1_ba    = (const float*)d_in[wbase + 10];
    const float* c2_Wk    = (const float*)d_in[wbase + 11];
    const float* c2_bk    = (const float*)d_in[wbase + 12];
    const float* c2_Wq    = (const float*)d_in[wbase + 13];
    const float* c2_bq    = (const float*)d_in[wbase + 14];
    const float* c2_Wv    = (const float*)d_in[wbase + 15];
    const float* c2_bv    = (const float*)d_in[wbase + 16];
    const float* c2_a_rel = (const float*)d_in[wbase + 17];
    const float* c2_m_rel = (const float*)d_in[wbase + 18];
    const float* c2_p_rel = (const float*)d_in[wbase + 19];
    const float* c2_Wa    = (const float*)d_in[wbase + 20];
    const float* c2_ba    = (const float*)d_in[wbase + 21];
    const float* c2_skip  = (const float*)d_in[wbase + 22];
    const float* Wc       = (const float*)d_in[wbase + 23];
    const float* bc       = (const float*)d_in[wbase + 24];

    int N_TX = in_sizes[0] / 128;
    int N_M  = in_sizes[1] / 128;
    int E0 = in_sizes[ebase + 1];
    int E1 = in_sizes[ebase + 3];

    void* p;
    float *q_tx, *q_m, *agg_tx, *agg_m, *h_tx, *h_m;
    float *WA1, *bA1, *WB1, *bB1, *WA2, *bA2, *WB2, *bB2;
    __half *kv_tx, *kv_m;
    int *rowptr0, *rowptr1, *cursor0, *cursor1, *srcs0, *srcs1;
    cudaGetSymbolAddress(&p, g_q_tx);    q_tx    = (float*)p;
    cudaGetSymbolAddress(&p, g_q_m);     q_m     = (float*)p;
    cudaGetSymbolAddress(&p, g_kv_tx);   kv_tx   = (__half*)p;
    cudaGetSymbolAddress(&p, g_kv_m);    kv_m    = (__half*)p;
    cudaGetSymbolAddress(&p, g_agg_tx);  agg_tx  = (float*)p;
    cudaGetSymbolAddress(&p, g_agg_m);   agg_m   = (float*)p;
    cudaGetSymbolAddress(&p, g_h_tx);    h_tx    = (float*)p;
    cudaGetSymbolAddress(&p, g_h_m);     h_m     = (float*)p;
    cudaGetSymbolAddress(&p, g_WA1);     WA1     = (float*)p;
    cudaGetSymbolAddress(&p, g_bA1);     bA1     = (float*)p;
    cudaGetSymbolAddress(&p, g_WB1);     WB1     = (float*)p;
    cudaGetSymbolAddress(&p, g_bB1);     bB1     = (float*)p;
    cudaGetSymbolAddress(&p, g_WA2);     WA2     = (float*)p;
    cudaGetSymbolAddress(&p, g_bA2);     bA2     = (float*)p;
    cudaGetSymbolAddress(&p, g_WB2);     WB2     = (float*)p;
    cudaGetSymbolAddress(&p, g_bB2);     bB2     = (float*)p;
    cudaGetSymbolAddress(&p, g_rowptr0); rowptr0 = (int*)p;
    cudaGetSymbolAddress(&p, g_rowptr1); rowptr1 = (int*)p;
    cudaGetSymbolAddress(&p, g_cursor0); cursor0 = (int*)p;
    cudaGetSymbolAddress(&p, g_cursor1); cursor1 = (int*)p;
    cudaGetSymbolAddress(&p, g_srcs0);   srcs0   = (int*)p;
    cudaGetSymbolAddress(&p, g_srcs1);   srcs1   = (int*)p;

    int gbTX = (N_TX + 127) / 128;
    int gbM  = (N_M + 127) / 128;
    int gbTX64 = (N_TX + 63) / 64;
    int gbM64  = (N_M + 63) / 64;

    ScatJob sjNone = {};
    sjNone.nblocks = 0;

    // ---- 1: effective weights + cursor zeroing ----
    {
        int zx = (N_M + N_TX + 255) / 256;
        int gx = zx > 97 ? zx : 97;
        eff_all_kernel<<<dim3(gx, 5), 256>>>(
            c1_Wq, c1_bq, c1_Wk, c1_bk, c1_Wv, c1_bv, c1_a_rel, c1_m_rel,
            c2_Wq, c2_bq, c2_Wk, c2_bk, c2_Wv, c2_bv, c2_a_rel, c2_m_rel,
            WA1, bA1, WB1, bB1, WA2, bA2, WB2, bB2,
            cursor0, N_M, cursor1, N_TX);
    }

    // ---- 2-3: hist + scan ----
    hist_both_kernel<<<(E0 + E1 + 255) / 256, 256>>>(tm_dst, E0, cursor0, mt_dst, E1, cursor1);
    scan_both_kernel<<<2, 1024>>>(cursor0, rowptr0, N_M, cursor1, rowptr1, N_TX);

    // ---- 4: scatter + layer-1 QKV GEMM fused (64 rows x 192 cols: A staged ONCE) ----
    {
        ScatJob sj = { tm_src, tm_dst, E0, cursor0, srcs0,
                       mt_src, mt_dst, E1, cursor1, srcs1,
                       (E0 + E1 + 255) / 256 };
        GemmJob j0 = { x_tx, WA1, bA1, nullptr, q_tx, kv_tx, N_TX, 192, 0, 64, 1 };
        GemmJob j1 = { x_m,  WB1, bB1, nullptr, q_m,  kv_m,  N_M,  192, 0, 64, 1 };
        mma_gemm_kernel<0, 0, 64, 192, 1, 0><<<sj.nblocks + gbTX64 + gbM64, 256>>>(
            j0, j1, gbTX64, 128, nullptr, sj, nullptr, nullptr);
    }

    // ---- 5: layer-1 attention, both directions merged ----
    {
        AttnSet s0 = { kv_tx, q_m,  rowptr0, srcs0, c1_p_rel,     agg_m,  N_M };
        AttnSet s1 = { kv_m,  q_tx, rowptr1, srcs1, c1_p_rel + 4, agg_tx, N_TX };
        attn_kernel<<<(N_M + N_TX + 7) / 8, 256>>>(s0, s1);
    }

    // ---- 6: layer-1 epilogue, tx + m merged: h = relu(gelu(agg) @ Wa + ba) ----
    {
        GemmJob j0 = { agg_tx, c1_Wa,        c1_ba,      nullptr, h_tx, nullptr, N_TX, 64, 0, 64, 1 };
        GemmJob j1 = { agg_m,  c1_Wa + 4096, c1_ba + 64, nullptr, h_m,  nullptr, N_M,  64, 0, 64, 1 };
        mma_gemm_kernel<1, 1, 128, 64, 0, 0><<<gbTX + gbM, 256>>>(
            j0, j1, gbTX, 64, nullptr, sjNone, nullptr, nullptr);
    }

    // ---- 7: layer-2 projections merged: tx Q (cols 0..63) + m KV (cols 64..191) ----
    {
        GemmJob j0 = { h_tx, WA2, bA2, nullptr, q_tx,    nullptr, N_TX, 192, 0,  64, 1 };
        GemmJob j1 = { h_m,  WB2, bB2, nullptr, nullptr, kv_m,    N_M,  192, 64, 0,  2 };
        mma_gemm_kernel<0, 0, 128, 64, 0, 0><<<gbTX + gbM * 2, 256>>>(
            j0, j1, gbTX, 64, nullptr, sjNone, nullptr, nullptr);
    }

    // ---- 8: layer-2 attention (tx dst only) ----
    {
        AttnSet s1 = { kv_m, q_tx, rowptr1, srcs1, c2_p_rel + 4, agg_tx, N_TX };
        AttnSet s0 = s1; s0.n = 0;
        attn_kernel<<<(N_TX + 7) / 8, 256>>>(s0, s1);
    }

    // ---- 9: layer-2 epilogue + skip mix + fused final logits -> d_out ----
    {
        GemmJob j0 = { agg_tx, c2_Wa, c2_ba, h_tx, (float*)d_out, nullptr, N_TX, 64, 0, 1, 1 };
        mma_gemm_kernel<2, 1, 128, 64, 0, 1><<<gbTX, 256>>>(
            j0, j0, gbTX, 64, c2_skip, sjNone, Wc, bc);
    }
}

// round 14
// speedup vs baseline: 1.0858x; 1.0423x over previous
#include <cuda_runtime.h>
#include <cuda_bf16.h>
#include <cuda_fp16.h>
#include <cstdint>

#define NTX_MAX 100000
#define NM_MAX  20000
#define E_MAX   500000

typedef __nv_bfloat16 bf16;

// ---------------- scratch (static device globals; no runtime allocation) ----------------
__device__ float  g_q_tx [(size_t)NTX_MAX * 64];   // fp32 Q
__device__ float  g_q_m  [(size_t)NM_MAX  * 64];
__device__ __half g_kv_tx[(size_t)NTX_MAX * 128];  // fp16 [Khat | Vhat]
__device__ __half g_kv_m [(size_t)NM_MAX  * 128];
__device__ float  g_agg_tx[(size_t)NTX_MAX * 64];
__device__ float  g_agg_m [(size_t)NM_MAX  * 64];
__device__ float  g_h_tx  [(size_t)NTX_MAX * 64];  // fp32 (skip input for L2 epilogue)
__device__ float  g_WA1[128 * 192];  __device__ float g_bA1[192];
__device__ float  g_WB1[128 * 192];  __device__ float g_bB1[192];
__device__ float  g_WA2[128 * 192];  __device__ float g_bA2[192];
__device__ float  g_WB2[128 * 192];  __device__ float g_bB2[192];
// CSR
__device__ int g_rowptr0[NM_MAX + 1];   // dst = m   (tx->m edges)
__device__ int g_rowptr1[NTX_MAX + 1];  // dst = tx  (m->tx edges)
__device__ int g_cursor0[NM_MAX];
__device__ int g_cursor1[NTX_MAX];
__device__ int g_srcs0[E_MAX];
__device__ int g_srcs1[E_MAX];

// ---------------- CSR build ----------------
__global__ void hist_both_kernel(const int* __restrict__ d0, int E0, int* __restrict__ c0,
                                 const int* __restrict__ d1, int E1, int* __restrict__ c1) {
    int e = blockIdx.x * blockDim.x + threadIdx.x;
    if (e < E0) atomicAdd(&c0[d0[e]], 1);
    else if (e < E0 + E1) atomicAdd(&c1[d1[e - E0]], 1);
}

__global__ void scan_both_kernel(int* __restrict__ cnt0, int* __restrict__ rp0, int n0,
                                 int* __restrict__ cnt1, int* __restrict__ rp1, int n1) {
    __shared__ int ssum[1024];
    int* cnt = blockIdx.x ? cnt1 : cnt0;
    int* rowptr = blockIdx.x ? rp1 : rp0;
    int n = blockIdx.x ? n1 : n0;
    int tid = threadIdx.x;
    int chunk = (n + 1023) / 1024;
    int start = tid * chunk;
    int end = start + chunk; if (end > n) end = n; if (start > n) start = n;
    int s = 0;
    for (int i = start; i < end; i++) s += cnt[i];
    ssum[tid] = s;
    __syncthreads();
    for (int off = 1; off < 1024; off <<= 1) {
        int v = (tid >= off) ? ssum[tid - off] : 0;
        __syncthreads();
        ssum[tid] += v;
        __syncthreads();
    }
    int run = (tid == 0) ? 0 : ssum[tid - 1];
    for (int i = start; i < end; i++) {
        int c = cnt[i];
        rowptr[i] = run;
        cnt[i] = run;       // cursor = rowptr (cnt doubles as cursor)
        run += c;
    }
    if (tid == 1023) rowptr[n] = run;
}

// ---------------- effective fused weights + CSR zeroing, one launch ----------------
__global__ void eff_all_kernel(
    const float* c1_Wq, const float* c1_bq, const float* c1_Wk, const float* c1_bk,
    const float* c1_Wv, const float* c1_bv, const float* c1_a, const float* c1_m,
    const float* c2_Wq, const float* c2_bq, const float* c2_Wk, const float* c2_bk,
    const float* c2_Wv, const float* c2_bv, const float* c2_a, const float* c2_m,
    float* WA1, float* bA1, float* WB1, float* bB1,
    float* WA2, float* bA2, float* WB2, float* bB2,
    int* cur0, int n0, int* cur1, int n1) {
    int y = blockIdx.y;
    int idx = blockIdx.x * blockDim.x + threadIdx.x;
    if (y == 4) {
        if (idx < n0) cur0[idx] = 0;
        else if (idx < n0 + n1) cur1[idx - n0] = 0;
        return;
    }
    int layer = y >> 1, typ = y & 1;
    int din = layer ? 64 : 128;
    int total = (din + 1) * 192;
    if (idx >= total) return;
    const float* Wq = layer ? c2_Wq : c1_Wq;  const float* bq = layer ? c2_bq : c1_bq;
    const float* Wk = layer ? c2_Wk : c1_Wk;  const float* bk = layer ? c2_bk : c1_bk;
    const float* Wv = layer ? c2_Wv : c1_Wv;  const float* bv = layer ? c2_bv : c1_bv;
    const float* ar = layer ? c2_a : c1_a;    const float* mr = layer ? c2_m : c1_m;
    Wq += (size_t)typ * din * 64; bq += typ * 64;
    Wk += (size_t)typ * din * 64; bk += typ * 64;
    Wv += (size_t)typ * din * 64; bv += typ * 64;
    ar += typ * 1024; mr += typ * 1024;
    float* Wout = layer ? (typ ? WB2 : WA2) : (typ ? WB1 : WA1);
    float* bout = layer ? (typ ? bB2 : bA2) : (typ ? bB1 : bA1);

    int i = idx / 192, c = idx % 192;
    bool isBias = (i == din);
    float val;
    if (c < 64) {
        val = isBias ? bq[c] : Wq[i * 64 + c];
    } else {
        int cc = c - 64;
        bool isV = (cc >= 64);
        if (isV) cc -= 64;
        int h = cc >> 4, e = cc & 15;
        const float* rel  = isV ? mr : ar;
        const float* Wsrc = isV ? Wv : Wk;
        const float* bsrc = isV ? bv : bk;
        float s = 0.f;
        #pragma unroll
        for (int d = 0; d < 16; d++) {
            float w = isBias ? bsrc[h * 16 + d] : Wsrc[i * 64 + h * 16 + d];
            s += w * rel[h * 256 + d * 16 + e];
        }
        val = s;
    }
    if (isBias) bout[c] = val;
    else        Wout[i * 192 + c] = val;
}

// ---------------- common GEMM device helpers ----------------
__device__ __forceinline__ void ldsm_x4(uint32_t* r, uint32_t addr) {
    asm volatile("ldmatrix.sync.aligned.m8n8.x4.shared.b16 {%0,%1,%2,%3}, [%4];"
        : "=r"(r[0]), "=r"(r[1]), "=r"(r[2]), "=r"(r[3]) : "r"(addr));
}
__device__ __forceinline__ void ldsm_x4_t(uint32_t* r, uint32_t addr) {
    asm volatile("ldmatrix.sync.aligned.m8n8.x4.trans.shared.b16 {%0,%1,%2,%3}, [%4];"
        : "=r"(r[0]), "=r"(r[1]), "=r"(r[2]), "=r"(r[3]) : "r"(addr));
}
__device__ __forceinline__ void mma_bf16(float* c, const uint32_t* a, uint32_t b0, uint32_t b1) {
    asm volatile("mma.sync.aligned.m16n8k16.row.col.f32.bf16.bf16.f32 "
        "{%0,%1,%2,%3}, {%4,%5,%6,%7}, {%8,%9}, {%0,%1,%2,%3};"
        : "+f"(c[0]), "+f"(c[1]), "+f"(c[2]), "+f"(c[3])
        : "r"(a[0]), "r"(a[1]), "r"(a[2]), "r"(a[3]), "r"(b0), "r"(b1));
}

__device__ __forceinline__ void split2(float x, float y, uint32_t& hi, uint32_t& lo) {
    bf16 hx = __float2bfloat16_rn(x), hy = __float2bfloat16_rn(y);
    bf16 lx = __float2bfloat16_rn(x - __bfloat162float(hx));
    bf16 ly = __float2bfloat16_rn(y - __bfloat162float(hy));
    __nv_bfloat162 h2 = __halves2bfloat162(hx, hy);
    __nv_bfloat162 l2 = __halves2bfloat162(lx, ly);
    hi = *(uint32_t*)&h2;
    lo = *(uint32_t*)&l2;
}

__device__ __forceinline__ float gelu_exact(float v) {
    return 0.5f * v * (1.f + erff(v * 0.70710678118654752f));
}

#define AS_STRIDE 40   // 32 + 8 pad (bf16 elems): conflict-free ldmatrix

struct GemmJob {
    const float* A; const float* B; const float* bias; const float* x_in;
    float* outF; __half* outH;
    int N, ldb, col0, ldo, colBlocks;
};

struct ScatJob {
    const int* s0; const int* d0; int E0; int* cur0; int* out0;
    const int* s1; const int* d1; int E1; int* cur1; int* out1;
    int nblocks;
};

// ---------------- generic 128-row GEMM (R10) ----------------
template <int POST, int AGELU, int NCOLS, int SCAT, int FINAL>
__global__ __launch_bounds__(256) void mma_gemm_kernel(
    GemmJob j0, GemmJob j1, int nb0, int DIN, const float* __restrict__ skipv,
    ScatJob sj, const float* __restrict__ Wc, const float* __restrict__ bc) {
    constexpr int NH = NCOLS / 2;
    constexpr int J2N = NH / 16;
    constexpr int JN = NH / 8;
    constexpr int BSTR = NCOLS + 8;
    constexpr int BQ = NCOLS / 4;
    constexpr int NB = NCOLS / 32;
    __shared__ bf16 As[2][128 * AS_STRIDE];
    __shared__ bf16 Bs[2][32 * BSTR];
    __shared__ float sred[FINAL ? 128 : 1];

    int t = threadIdx.x;
    if (SCAT) {
        if (blockIdx.x < (unsigned)sj.nblocks) {
            int e = blockIdx.x * 256 + t;
            if (e < sj.E0) {
                int p = atomicAdd(&sj.cur0[sj.d0[e]], 1);
                sj.out0[p] = sj.s0[e];
            } else if (e < sj.E0 + sj.E1) {
                int ee = e - sj.E0;
                int p = atomicAdd(&sj.cur1[sj.d1[ee]], 1);
                sj.out1[p] = sj.s1[ee];
            }
            return;
        }
    }
    int bx = blockIdx.x - (SCAT ? sj.nblocks : 0);
    bool second = bx >= nb0;
    GemmJob J = second ? j1 : j0;
    int b = second ? bx - nb0 : bx;
    int rb, cb;
    if (J.colBlocks == 2) { rb = b >> 1; cb = b & 1; } else { rb = b; cb = 0; }
    int row0 = rb * 128;
    int colW = J.col0 + cb * NCOLS;

    int w = t >> 5, lane = t & 31;
    int mbase = (w >> 1) * 32;
    int nbase = (w & 1) * NH;
    int lrow = lane & 15;
    int lcolo = (lane >> 4) * 8;

    uint32_t a_base0 = (uint32_t)__cvta_generic_to_shared(&As[0][0]);
    uint32_t a_base1 = (uint32_t)__cvta_generic_to_shared(&As[1][0]);
    uint32_t b_base0 = (uint32_t)__cvta_generic_to_shared(&Bs[0][0]);
    uint32_t b_base1 = (uint32_t)__cvta_generic_to_shared(&Bs[1][0]);

    float acc[2][JN][4];
    #pragma unroll
    for (int i = 0; i < 2; i++)
        #pragma unroll
        for (int j = 0; j < JN; j++)
            #pragma unroll
            for (int q = 0; q < 4; q++) acc[i][j][q] = 0.f;

    for (int k0 = 0; k0 < DIN; k0 += 32) {
        #pragma unroll
        for (int ii = 0; ii < 4; ii++) {
            int idx = t + ii * 256;
            int r = idx >> 3, q = idx & 7;
            int grow = row0 + r;
            float4 v = make_float4(0.f, 0.f, 0.f, 0.f);
            if (grow < J.N) v = *(const float4*)(J.A + (size_t)grow * DIN + k0 + q * 4);
            if (AGELU) {
                v.x = gelu_exact(v.x); v.y = gelu_exact(v.y);
                v.z = gelu_exact(v.z); v.w = gelu_exact(v.w);
            }
            uint32_t h0, l0, h1, l1;
            split2(v.x, v.y, h0, l0);
            split2(v.z, v.w, h1, l1);
            *(uint2*)(&As[0][r * AS_STRIDE + q * 4]) = make_uint2(h0, h1);
            *(uint2*)(&As[1][r * AS_STRIDE + q * 4]) = make_uint2(l0, l1);
        }
        #pragma unroll
        for (int ii = 0; ii < NB; ii++) {
            int idx = t + ii * 256;
            int r = idx / BQ, q = idx % BQ;
            float4 v = *(const float4*)(J.B + (size_t)(k0 + r) * J.ldb + colW + q * 4);
            uint32_t h0, l0, h1, l1;
            split2(v.x, v.y, h0, l0);
            split2(v.z, v.w, h1, l1);
            *(uint2*)(&Bs[0][r * BSTR + q * 4]) = make_uint2(h0, h1);
            *(uint2*)(&Bs[1][r * BSTR + q * 4]) = make_uint2(l0, l1);
        }
        __syncthreads();

        #pragma unroll
        for (int kb = 0; kb < 32; kb += 16) {
            uint32_t ah[2][4], al[2][4];
            #pragma unroll
            for (int i = 0; i < 2; i++) {
                uint32_t off = (uint32_t)(((mbase + i * 16 + lrow) * AS_STRIDE + kb + lcolo) * 2);
                ldsm_x4(ah[i], a_base0 + off);
                ldsm_x4(al[i], a_base1 + off);
            }
            #pragma unroll
            for (int j2 = 0; j2 < J2N; j2++) {
                uint32_t bh[4], bl[4];
                uint32_t off = (uint32_t)(((kb + lrow) * BSTR + nbase + j2 * 16 + lcolo) * 2);
                ldsm_x4_t(bh, b_base0 + off);
                ldsm_x4_t(bl, b_base1 + off);
                #pragma unroll
                for (int i = 0; i < 2; i++)
                    #pragma unroll
                    for (int jj = 0; jj < 2; jj++) {
                        int j = j2 * 2 + jj, o = jj * 2;
                        mma_bf16(acc[i][j], ah[i], bh[o], bh[o + 1]);
                        mma_bf16(acc[i][j], ah[i], bl[o], bl[o + 1]);
                        mma_bf16(acc[i][j], al[i], bh[o], bh[o + 1]);
                    }
            }
        }
        __syncthreads();
    }

    int g = lane >> 2, tq = lane & 3;
    float amix = 0.f;
    if (POST == 2) amix = 1.f / (1.f + __expf(-skipv[0]));
    float fpart[2][2];
    if (FINAL) { fpart[0][0] = fpart[0][1] = fpart[1][0] = fpart[1][1] = 0.f; }
    #pragma unroll
    for (int i = 0; i < 2; i++) {
        #pragma unroll
        for (int j = 0; j < JN; j++) {
            int colg = colW + nbase + j * 8 + tq * 2;
            float b0 = J.bias[colg], b1 = J.bias[colg + 1];
            #pragma unroll
            for (int half = 0; half < 2; half++) {
                int row = row0 + mbase + i * 16 + g + half * 8;
                if (row < J.N) {
                    float o0 = acc[i][j][half * 2 + 0] + b0;
                    float o1 = acc[i][j][half * 2 + 1] + b1;
                    if (POST == 1) { o0 = fmaxf(o0, 0.f); o1 = fmaxf(o1, 0.f); }
                    if (POST == 2) {
                        o0 = amix * o0 + (1.f - amix) * J.x_in[(size_t)row * 64 + colg];
                        o1 = amix * o1 + (1.f - amix) * J.x_in[(size_t)row * 64 + colg + 1];
                    }
                    if (FINAL) {
                        fpart[i][half] += o0 * Wc[colg] + o1 * Wc[colg + 1];
                    } else if (J.outH != nullptr && colg >= 64) {
                        __half2 hv = __floats2half2_rn(o0, o1);
                        *(__half2*)(J.outH + (size_t)row * 128 + (colg - 64)) = hv;
                    } else {
                        *(float2*)(J.outF + (size_t)row * J.ldo + colg) = make_float2(o0, o1);
                    }
                }
            }
        }
    }
    if (FINAL) {
        #pragma unroll
        for (int i = 0; i < 2; i++)
            #pragma unroll
            for (int half = 0; half < 2; half++) {
                float pv = fpart[i][half];
                pv += __shfl_xor_sync(0xffffffffu, pv, 1);
                pv += __shfl_xor_sync(0xffffffffu, pv, 2);
                fpart[i][half] = pv;
            }
        if ((w & 1) == 0 && tq == 0) {
            #pragma unroll
            for (int i = 0; i < 2; i++)
                #pragma unroll
                for (int half = 0; half < 2; half++)
                    sred[mbase + i * 16 + g + half * 8] = fpart[i][half];
        }
        __syncthreads();
        if ((w & 1) == 1 && tq == 0) {
            #pragma unroll
            for (int i = 0; i < 2; i++)
                #pragma unroll
                for (int half = 0; half < 2; half++) {
                    int local = mbase + i * 16 + g + half * 8;
                    int row = row0 + local;
                    if (row < J.N)
                        J.outF[row] = sred[local] + fpart[i][half] + bc[0];
                }
        }
    }
}

// ---------------- fused L1-epilogue + L2-projection kernel ----------------
// Per 128-row block:
//   GEMM1: h = relu( gelu(agg) @ Wa + ba )   (K=64, 64 cols)
//   h kept in smem as bf16 hi/lo (fp32 h also written to gmem if hOut)
//   GEMM2: out = h @ W2[:, colW:colW+64] + b2  -> fp32 q or fp16 kv
#define FA_STR 72   // 64 + 8 pad

struct FuseJob {
    const float* agg; const float* Wa; const float* ba;
    const float* W2;  const float* b2;   // W2 ldb = 192
    float* hOut;                          // fp32 h (tx) or nullptr
    float* qOut; __half* kvOut;           // GEMM2 output (one of them set)
    int N, colBlocks, col0;               // GEMM2 colW = col0 + cb*64
};

__global__ __launch_bounds__(256) void fuse_epi_proj_kernel(FuseJob j0, FuseJob j1, int nb0) {
    extern __shared__ __align__(16) char dsm[];
    bf16* Ah = (bf16*)dsm;                 // 128 x FA_STR
    bf16* Al = Ah + 128 * FA_STR;
    bf16* Bh = Al + 128 * FA_STR;          // 64 x FA_STR
    bf16* Bl = Bh + 64 * FA_STR;

    int t = threadIdx.x;
    int bx = blockIdx.x;
    bool second = bx >= nb0;
    FuseJob J = second ? j1 : j0;
    int b = second ? bx - nb0 : bx;
    int rb, cb;
    if (J.colBlocks == 2) { rb = b >> 1; cb = b & 1; } else { rb = b; cb = 0; }
    int row0 = rb * 128;
    int colW = J.col0 + cb * 64;

    int w = t >> 5, lane = t & 31;
    int mbase = (w >> 1) * 32;
    int nbase = (w & 1) * 32;
    int lrow = lane & 15;
    int lcolo = (lane >> 4) * 8;
    int g = lane >> 2, tq = lane & 3;

    uint32_t AhS = (uint32_t)__cvta_generic_to_shared(Ah);
    uint32_t AlS = (uint32_t)__cvta_generic_to_shared(Al);
    uint32_t BhS = (uint32_t)__cvta_generic_to_shared(Bh);
    uint32_t BlS = (uint32_t)__cvta_generic_to_shared(Bl);

    // ---- stage GEMM1 inputs: agg (gelu+split, full 128x64) and Wa (full 64x64) ----
    #pragma unroll
    for (int ii = 0; ii < 8; ii++) {
        int idx = t + ii * 256;       // 0..2047
        int r = idx >> 4, q = idx & 15;
        int grow = row0 + r;
        float4 v = make_float4(0.f, 0.f, 0.f, 0.f);
        if (grow < J.N) v = *(const float4*)(J.agg + (size_t)grow * 64 + q * 4);
        v.x = gelu_exact(v.x); v.y = gelu_exact(v.y);
        v.z = gelu_exact(v.z); v.w = gelu_exact(v.w);
        uint32_t h0, l0, h1, l1;
        split2(v.x, v.y, h0, l0);
        split2(v.z, v.w, h1, l1);
        *(uint2*)(&Ah[r * FA_STR + q * 4]) = make_uint2(h0, h1);
        *(uint2*)(&Al[r * FA_STR + q * 4]) = make_uint2(l0, l1);
    }
    #pragma unroll
    for (int ii = 0; ii < 4; ii++) {
        int idx = t + ii * 256;       // 0..1023
        int r = idx >> 4, q = idx & 15;
        float4 v = *(const float4*)(J.Wa + (size_t)r * 64 + q * 4);
        uint32_t h0, l0, h1, l1;
        split2(v.x, v.y, h0, l0);
        split2(v.z, v.w, h1, l1);
        *(uint2*)(&Bh[r * FA_STR + q * 4]) = make_uint2(h0, h1);
        *(uint2*)(&Bl[r * FA_STR + q * 4]) = make_uint2(l0, l1);
    }
    __syncthreads();

    // ---- GEMM1 MMA: K = 64 ----
    float acc[2][4][4];
    #pragma unroll
    for (int i = 0; i < 2; i++)
        #pragma unroll
        for (int j = 0; j < 4; j++)
            #pragma unroll
            for (int q = 0; q < 4; q++) acc[i][j][q] = 0.f;

    #pragma unroll
    for (int kb = 0; kb < 64; kb += 16) {
        uint32_t ah[2][4], al[2][4];
        #pragma unroll
        for (int i = 0; i < 2; i++) {
            uint32_t off = (uint32_t)(((mbase + i * 16 + lrow) * FA_STR + kb + lcolo) * 2);
            ldsm_x4(ah[i], AhS + off);
            ldsm_x4(al[i], AlS + off);
        }
        #pragma unroll
        for (int j2 = 0; j2 < 2; j2++) {
            uint32_t bh[4], bl[4];
            uint32_t off = (uint32_t)(((kb + lrow) * FA_STR + nbase + j2 * 16 + lcolo) * 2);
            ldsm_x4_t(bh, BhS + off);
            ldsm_x4_t(bl, BlS + off);
            #pragma unroll
            for (int i = 0; i < 2; i++)
                #pragma unroll
                for (int jj = 0; jj < 2; jj++) {
                    int j = j2 * 2 + jj, o = jj * 2;
                    mma_bf16(acc[i][j], ah[i], bh[o], bh[o + 1]);
                    mma_bf16(acc[i][j], ah[i], bl[o], bl[o + 1]);
                    mma_bf16(acc[i][j], al[i], bh[o], bh[o + 1]);
                }
        }
    }
    __syncthreads();   // all GEMM1 smem reads done

    // ---- epilogue1: h = relu(acc + ba); store h splits into A smem (+ gmem fp32 if hOut) ----
    // ---- and stage GEMM2 B (W2 slice) into B smem (overwrite Wa) ----
    #pragma unroll
    for (int i = 0; i < 2; i++) {
        #pragma unroll
        for (int j = 0; j < 4; j++) {
            int col = nbase + j * 8 + tq * 2;
            float b0 = J.ba[col], b1 = J.ba[col + 1];
            #pragma unroll
            for (int half = 0; half < 2; half++) {
                int lrowi = mbase + i * 16 + g + half * 8;
                int row = row0 + lrowi;
                float o0 = fmaxf(acc[i][j][half * 2 + 0] + b0, 0.f);
                float o1 = fmaxf(acc[i][j][half * 2 + 1] + b1, 0.f);
                if (J.hOut != nullptr && row < J.N)
                    *(float2*)(J.hOut + (size_t)row * 64 + col) = make_float2(o0, o1);
                uint32_t hv, lv;
                split2(o0, o1, hv, lv);
                *(uint32_t*)(&Ah[lrowi * FA_STR + col]) = hv;
                *(uint32_t*)(&Al[lrowi * FA_STR + col]) = lv;
            }
        }
    }
    #pragma unroll
    for (int ii = 0; ii < 4; ii++) {
        int idx = t + ii * 256;
        int r = idx >> 4, q = idx & 15;
        float4 v = *(const float4*)(J.W2 + (size_t)r * 192 + colW + q * 4);
        uint32_t h0, l0, h1, l1;
        split2(v.x, v.y, h0, l0);
        split2(v.z, v.w, h1, l1);
        *(uint2*)(&Bh[r * FA_STR + q * 4]) = make_uint2(h0, h1);
        *(uint2*)(&Bl[r * FA_STR + q * 4]) = make_uint2(l0, l1);
    }
    __syncthreads();

    // ---- GEMM2 MMA: K = 64 (A = h splits already in smem) ----
    #pragma unroll
    for (int i = 0; i < 2; i++)
        #pragma unroll
        for (int j = 0; j < 4; j++)
            #pragma unroll
            for (int q = 0; q < 4; q++) acc[i][j][q] = 0.f;

    #pragma unroll
    for (int kb = 0; kb < 64; kb += 16) {
        uint32_t ah[2][4], al[2][4];
        #pragma unroll
        for (int i = 0; i < 2; i++) {
            uint32_t off = (uint32_t)(((mbase + i * 16 + lrow) * FA_STR + kb + lcolo) * 2);
            ldsm_x4(ah[i], AhS + off);
            ldsm_x4(al[i], AlS + off);
        }
        #pragma unroll
        for (int j2 = 0; j2 < 2; j2++) {
            uint32_t bh[4], bl[4];
            uint32_t off = (uint32_t)(((kb + lrow) * FA_STR + nbase + j2 * 16 + lcolo) * 2);
            ldsm_x4_t(bh, BhS + off);
            ldsm_x4_t(bl, BlS + off);
            #pragma unroll
            for (int i = 0; i < 2; i++)
                #pragma unroll
                for (int jj = 0; jj < 2; jj++) {
                    int j = j2 * 2 + jj, o = jj * 2;
                    mma_bf16(acc[i][j], ah[i], bh[o], bh[o + 1]);
                    mma_bf16(acc[i][j], ah[i], bl[o], bl[o + 1]);
                    mma_bf16(acc[i][j], al[i], bh[o], bh[o + 1]);
                }
        }
    }

    // ---- epilogue2: out = acc + b2 ----
    #pragma unroll
    for (int i = 0; i < 2; i++) {
        #pragma unroll
        for (int j = 0; j < 4; j++) {
            int col = nbase + j * 8 + tq * 2;
            int colg = colW + col;
            float b0 = J.b2[colg], b1 = J.b2[colg + 1];
            #pragma unroll
            for (int half = 0; half < 2; half++) {
                int row = row0 + mbase + i * 16 + g + half * 8;
                if (row < J.N) {
                    float o0 = acc[i][j][half * 2 + 0] + b0;
                    float o1 = acc[i][j][half * 2 + 1] + b1;
                    if (J.kvOut != nullptr) {
                        __half2 hv = __floats2half2_rn(o0, o1);
                        *(__half2*)(J.kvOut + (size_t)row * 128 + (colg - 64)) = hv;
                    } else {
                        *(float2*)(J.qOut + (size_t)row * 64 + colg) = make_float2(o0, o1);
                    }
                }
            }
        }
    }
}

// ---------------- attention (merged over both dst sets) ----------------
struct AttnSet {
    const __half* kv; const float* q;
    const int* rp; const int* srcs;
    const float* prel; float* agg; int n;
};

__global__ __launch_bounds__(256) void attn_kernel(AttnSet s0, AttnSet s1) {
    int w = threadIdx.x >> 5, lane = threadIdx.x & 31;
    int d = blockIdx.x * 8 + w;
    AttnSet S;
    int dst;
    if (d < s0.n) { S = s0; dst = d; }
    else {
        dst = d - s0.n;
        if (dst >= s1.n) return;
        S = s1;
    }
    int sub = lane & 7;
    int eg = lane >> 3;
    const float* qd = S.q + (size_t)dst * 64 + sub * 8;
    float4 q0 = *(const float4*)(qd);
    float4 q1 = *(const float4*)(qd + 4);
    float pr = S.prel[sub >> 1] * 0.25f;   // /SQRT_D folded
    float4 a0 = make_float4(0.f, 0.f, 0.f, 0.f);
    float4 a1 = make_float4(0.f, 0.f, 0.f, 0.f);
    float den = 0.f;
    int beg = S.rp[dst], end = S.rp[dst + 1];
    for (int i = beg; i < end; i += 4) {
        int ei = i + eg;
        bool valid = ei < end;
        int s = S.srcs[valid ? ei : beg];
        const __half* ps = S.kv + (size_t)s * 128 + sub * 8;
        uint4 kraw = *(const uint4*)(ps);        // 8 halfs: K slice
        uint4 vraw = *(const uint4*)(ps + 64);   // 8 halfs: V slice
        float2 k0 = __half22float2(*(__half2*)&kraw.x);
        float2 k1 = __half22float2(*(__half2*)&kraw.y);
        float2 k2 = __half22float2(*(__half2*)&kraw.z);
        float2 k3 = __half22float2(*(__half2*)&kraw.w);
        float part = q0.x * k0.x + q0.y * k0.y + q0.z * k1.x + q0.w * k1.y
                   + q1.x * k2.x + q1.y * k2.y + q1.z * k3.x + q1.w * k3.y;
        part += __shfl_xor_sync(0xffffffffu, part, 1);
        float e = valid ? __expf(part * pr) : 0.f;
        float2 v0 = __half22float2(*(__half2*)&vraw.x);
        float2 v1 = __half22float2(*(__half2*)&vraw.y);
        float2 v2 = __half22float2(*(__half2*)&vraw.z);
        float2 v3 = __half22float2(*(__half2*)&vraw.w);
        a0.x = fmaf(e, v0.x, a0.x); a0.y = fmaf(e, v0.y, a0.y);
        a0.z = fmaf(e, v1.x, a0.z); a0.w = fmaf(e, v1.y, a0.w);
        a1.x = fmaf(e, v2.x, a1.x); a1.y = fmaf(e, v2.y, a1.y);
        a1.z = fmaf(e, v3.x, a1.z); a1.w = fmaf(e, v3.y, a1.w);
        den += e;
    }
    #pragma unroll
    for (int off = 8; off <= 16; off <<= 1) {
        a0.x += __shfl_xor_sync(0xffffffffu, a0.x, off);
        a0.y += __shfl_xor_sync(0xffffffffu, a0.y, off);
        a0.z += __shfl_xor_sync(0xffffffffu, a0.z, off);
        a0.w += __shfl_xor_sync(0xffffffffu, a0.w, off);
        a1.x += __shfl_xor_sync(0xffffffffu, a1.x, off);
        a1.y += __shfl_xor_sync(0xffffffffu, a1.y, off);
        a1.z += __shfl_xor_sync(0xffffffffu, a1.z, off);
        a1.w += __shfl_xor_sync(0xffffffffu, a1.w, off);
        den  += __shfl_xor_sync(0xffffffffu, den, off);
    }
    if (lane < 8) {
        float inv = 1.f / (den + 1e-16f);
        a0.x *= inv; a0.y *= inv; a0.z *= inv; a0.w *= inv;
        a1.x *= inv; a1.y *= inv; a1.z *= inv; a1.w *= inv;
        float* op = S.agg + (size_t)dst * 64 + sub * 8;
        *(float4*)(op) = a0;
        *(float4*)(op + 4) = a1;
    }
}

// ---------------- launch ----------------
extern "C" void kernel_launch(void* const* d_in, const int* in_sizes, int n_in,
                              void* d_out, int out_size) {
    (void)n_in; (void)out_size;
    int ebase, wbase;
    if (in_sizes[2] > 100000) { ebase = 2;  wbase = 6; }
    else                      { ebase = 27; wbase = 2; }

    const float* x_tx = (const float*)d_in[0];
    const float* x_m  = (const float*)d_in[1];
    const int* tm_src = (const int*)d_in[ebase + 0];
    const int* tm_dst = (const int*)d_in[ebase + 1];
    const int* mt_src = (const int*)d_in[ebase + 2];
    const int* mt_dst = (const int*)d_in[ebase + 3];

    const float* c1_Wk    = (const float*)d_in[wbase + 0];
    const float* c1_bk    = (const float*)d_in[wbase + 1];
    const float* c1_Wq    = (const float*)d_in[wbase + 2];
    const float* c1_bq    = (const float*)d_in[wbase + 3];
    const float* c1_Wv    = (const float*)d_in[wbase + 4];
    const float* c1_bv    = (const float*)d_in[wbase + 5];
    const float* c1_a_rel = (const float*)d_in[wbase + 6];
    const float* c1_m_rel = (const float*)d_in[wbase + 7];
    const float* c1_p_rel = (const float*)d_in[wbase + 8];
    const float* c1_Wa    = (const float*)d_in[wbase + 9];
    const float* c1_ba    = (const float*)d_in[wbase + 10];
    const float* c2_Wk    = (const float*)d_in[wbase + 11];
    const float* c2_bk    = (const float*)d_in[wbase + 12];
    const float* c2_Wq    = (const float*)d_in[wbase + 13];
    const float* c2_bq    = (const float*)d_in[wbase + 14];
    const float* c2_Wv    = (const float*)d_in[wbase + 15];
    const float* c2_bv    = (const float*)d_in[wbase + 16];
    const float* c2_a_rel = (const float*)d_in[wbase + 17];
    const float* c2_m_rel = (const float*)d_in[wbase + 18];
    const float* c2_p_rel = (const float*)d_in[wbase + 19];
    const float* c2_Wa    = (const float*)d_in[wbase + 20];
    const float* c2_ba    = (const float*)d_in[wbase + 21];
    const float* c2_skip  = (const float*)d_in[wbase + 22];
    const float* Wc       = (const float*)d_in[wbase + 23];
    const float* bc       = (const float*)d_in[wbase + 24];

    int N_TX = in_sizes[0] / 128;
    int N_M  = in_sizes[1] / 128;
    int E0 = in_sizes[ebase + 1];
    int E1 = in_sizes[ebase + 3];

    void* p;
    float *q_tx, *q_m, *agg_tx, *agg_m, *h_tx;
    float *WA1, *bA1, *WB1, *bB1, *WA2, *bA2, *WB2, *bB2;
    __half *kv_tx, *kv_m;
    int *rowptr0, *rowptr1, *cursor0, *cursor1, *srcs0, *srcs1;
    cudaGetSymbolAddress(&p, g_q_tx);    q_tx    = (float*)p;
    cudaGetSymbolAddress(&p, g_q_m);     q_m     = (float*)p;
    cudaGetSymbolAddress(&p, g_kv_tx);   kv_tx   = (__half*)p;
    cudaGetSymbolAddress(&p, g_kv_m);    kv_m    = (__half*)p;
    cudaGetSymbolAddress(&p, g_agg_tx);  agg_tx  = (float*)p;
    cudaGetSymbolAddress(&p, g_agg_m);   agg_m   = (float*)p;
    cudaGetSymbolAddress(&p, g_h_tx);    h_tx    = (float*)p;
    cudaGetSymbolAddress(&p, g_WA1);     WA1     = (float*)p;
    cudaGetSymbolAddress(&p, g_bA1);     bA1     = (float*)p;
    cudaGetSymbolAddress(&p, g_WB1);     WB1     = (float*)p;
    cudaGetSymbolAddress(&p, g_bB1);     bB1     = (float*)p;
    cudaGetSymbolAddress(&p, g_WA2);     WA2     = (float*)p;
    cudaGetSymbolAddress(&p, g_bA2);     bA2     = (float*)p;
    cudaGetSymbolAddress(&p, g_WB2);     WB2     = (float*)p;
    cudaGetSymbolAddress(&p, g_bB2);     bB2     = (float*)p;
    cudaGetSymbolAddress(&p, g_rowptr0); rowptr0 = (int*)p;
    cudaGetSymbolAddress(&p, g_rowptr1); rowptr1 = (int*)p;
    cudaGetSymbolAddress(&p, g_cursor0); cursor0 = (int*)p;
    cudaGetSymbolAddress(&p, g_cursor1); cursor1 = (int*)p;
    cudaGetSymbolAddress(&p, g_srcs0);   srcs0   = (int*)p;
    cudaGetSymbolAddress(&p, g_srcs1);   srcs1   = (int*)p;

    int gbTX = (N_TX + 127) / 128;
    int gbM  = (N_M + 127) / 128;

    ScatJob sjNone = {};
    sjNone.nblocks = 0;

    // ---- 1: effective weights + cursor zeroing ----
    {
        int zx = (N_M + N_TX + 255) / 256;
        int gx = zx > 97 ? zx : 97;
        eff_all_kernel<<<dim3(gx, 5), 256>>>(
            c1_Wq, c1_bq, c1_Wk, c1_bk, c1_Wv, c1_bv, c1_a_rel, c1_m_rel,
            c2_Wq, c2_bq, c2_Wk, c2_bk, c2_Wv, c2_bv, c2_a_rel, c2_m_rel,
            WA1, bA1, WB1, bB1, WA2, bA2, WB2, bB2,
            cursor0, N_M, cursor1, N_TX);
    }

    // ---- 2-3: hist + scan ----
    hist_both_kernel<<<(E0 + E1 + 255) / 256, 256>>>(tm_dst, E0, cursor0, mt_dst, E1, cursor1);
    scan_both_kernel<<<2, 1024>>>(cursor0, rowptr0, N_M, cursor1, rowptr1, N_TX);

    // ---- 4: scatter + layer-1 QKV GEMM fused (128 x 96 tiles) ----
    {
        ScatJob sj = { tm_src, tm_dst, E0, cursor0, srcs0,
                       mt_src, mt_dst, E1, cursor1, srcs1,
                       (E0 + E1 + 255) / 256 };
        GemmJob j0 = { x_tx, WA1, bA1, nullptr, q_tx, kv_tx, N_TX, 192, 0, 64, 2 };
        GemmJob j1 = { x_m,  WB1, bB1, nullptr, q_m,  kv_m,  N_M,  192, 0, 64, 2 };
        int nb0 = gbTX * 2;
        mma_gemm_kernel<0, 0, 96, 1, 0><<<sj.nblocks + nb0 + gbM * 2, 256>>>(
            j0, j1, nb0, 128, nullptr, sj, nullptr, nullptr);
    }

    // ---- 5: layer-1 attention, both directions merged ----
    {
        AttnSet s0 = { kv_tx, q_m,  rowptr0, srcs0, c1_p_rel,     agg_m,  N_M };
        AttnSet s1 = { kv_m,  q_tx, rowptr1, srcs1, c1_p_rel + 4, agg_tx, N_TX };
        attn_kernel<<<(N_M + N_TX + 7) / 8, 256>>>(s0, s1);
    }

    // ---- 6: FUSED layer-1 epilogue + layer-2 projection ----
    // tx: h_tx = relu(gelu(agg_tx)@Wa0+ba0) -> gmem fp32 + q_tx = h_tx@WA2[:,0:64]+bA2
    // m:  h_m  = relu(gelu(agg_m)@Wa1+ba1) (smem only) + kv_m = h_m@WB2[:,64:192]+bB2 (fp16)
    {
        const int DSM = (2 * 128 * FA_STR + 2 * 64 * FA_STR) * 2;  // 55296 B
        cudaFuncSetAttribute(fuse_epi_proj_kernel,
                             cudaFuncAttributeMaxDynamicSharedMemorySize, DSM);
        FuseJob j0 = { agg_tx, c1_Wa,        c1_ba,      WA2, bA2, h_tx,
                       q_tx, nullptr, N_TX, 1, 0 };
        FuseJob j1 = { agg_m,  c1_Wa + 4096, c1_ba + 64, WB2, bB2, nullptr,
                       nullptr, kv_m, N_M, 2, 64 };
        fuse_epi_proj_kernel<<<gbTX + gbM * 2, 256, DSM>>>(j0, j1, gbTX);
    }

    // ---- 7: layer-2 attention (tx dst only) ----
    {
        AttnSet s1 = { kv_m, q_tx, rowptr1, srcs1, c2_p_rel + 4, agg_tx, N_TX };
        AttnSet s0 = s1; s0.n = 0;
        attn_kernel<<<(N_TX + 7) / 8, 256>>>(s0, s1);
    }

    // ---- 8: layer-2 epilogue + skip mix + fused final logits -> d_out ----
    {
        GemmJob j0 = { agg_tx, c2_Wa, c2_ba, h_tx, (float*)d_out, nullptr, N_TX, 64, 0, 1, 1 };
        mma_gemm_kernel<2, 1, 64, 0, 1><<<gbTX, 256>>>(
            j0, j0, gbTX, 64, c2_skip, sjNone, Wc, bc);
    }
}